// round 3
// baseline (speedup 1.0000x reference)
#include <cuda_runtime.h>
#include <cuda_bf16.h>
#include <cstdint>

// ============================================================================
// Problem constants
//   x      [4, 128, 30000, 1] f32
//   ne_idx [4, 30000, 4]      i32
//   conv_w [256, 128, 1, 5]   f32
//   conv_b [256]              f32
//   out    [4, 256, 30000, 1] f32
//
// out[b,o,e] = sum_{c,k} G[b,c,e,k] * W[o,c,k] + bias[o]
//   G taps: [self, n0+n2, n1+n3, |n0-n2|, |n1-n3|]
// GEMM: [COUT=256] x [K'=640] x [B*E=120000], fp32 via 3-term bf16 split.
// NOTE: tcgen05/TMA unavailable (PTX targets compute_103, 'a'-features rejected)
// -> classic ldmatrix + mma.sync.m16n8k16 bf16 path.
// ============================================================================
static constexpr int BATCH = 4;
static constexpr int CIN   = 128;
static constexpr int COUT  = 256;
static constexpr int E     = 30000;
static constexpr int TAPS  = 5;

static constexpr int ETILE   = 128;
static constexpr int ETILES  = (E + ETILE - 1) / ETILE;   // 235
static constexpr int NBLOCKS = BATCH * ETILES;            // 940
static constexpr int NSTAGES = 10;                        // (tap 0..4) x (chalf 0..1)

// ============================================================================
// Device scratch (__device__ globals: allocation-free rule)
// ============================================================================
__device__ float g_xt[(size_t)BATCH * E * CIN];            // x transposed [B,E,C]
__device__ __nv_bfloat16 g_w[2 * TAPS * 2 * COUT * 64];    // [part][tap][chalf][n][64]
static constexpr int WPART_STRIDE = TAPS * 2 * COUT * 64;  // 163840

// ============================================================================
// Helpers
// ============================================================================
__device__ __forceinline__ uint32_t smem_u32(const void* p) {
    uint32_t a;
    asm("{ .reg .u64 t; cvta.to.shared.u64 t, %1; cvt.u32.u64 %0, t; }"
        : "=r"(a) : "l"(p));
    return a;
}

#define SMEM_SWIZZLE_128B(off) ((off) ^ (((off) >> 3) & 0x70))

__device__ __forceinline__ void ldsm_x4(uint32_t& r0, uint32_t& r1,
                                        uint32_t& r2, uint32_t& r3, uint32_t addr) {
    asm volatile("ldmatrix.sync.aligned.m8n8.x4.shared.b16 {%0,%1,%2,%3}, [%4];"
                 : "=r"(r0), "=r"(r1), "=r"(r2), "=r"(r3) : "r"(addr));
}

__device__ __forceinline__ void mma16816(float* c, const uint32_t* a, const uint32_t* b) {
    asm volatile(
        "mma.sync.aligned.m16n8k16.row.col.f32.bf16.bf16.f32 "
        "{%0,%1,%2,%3}, {%4,%5,%6,%7}, {%8,%9}, {%0,%1,%2,%3};"
        : "+f"(c[0]), "+f"(c[1]), "+f"(c[2]), "+f"(c[3])
        : "r"(a[0]), "r"(a[1]), "r"(a[2]), "r"(a[3]), "r"(b[0]), "r"(b[1]));
}

__device__ __forceinline__ uint32_t pack_bf16x2(__nv_bfloat16 a, __nv_bfloat16 b) {
    uint32_t ua = (uint32_t)__bfloat16_as_ushort(a);
    uint32_t ub = (uint32_t)__bfloat16_as_ushort(b);
    return ua | (ub << 16);
}

// ============================================================================
// Prep 1: transpose x [B,C,E] -> g_xt [B,E,C] (contiguous 512B rows per edge)
// ============================================================================
__global__ void transpose_kernel(const float* __restrict__ x) {
    __shared__ float tile[32][33];
    int b  = blockIdx.z;
    int c0 = blockIdx.y * 32;
    int e0 = blockIdx.x * 32;
    int tx = threadIdx.x, ty = threadIdx.y;

    #pragma unroll
    for (int i = ty; i < 32; i += 8) {
        int e = e0 + tx;
        float v = 0.f;
        if (e < E) v = x[((size_t)b * CIN + (c0 + i)) * E + e];
        tile[i][tx] = v;
    }
    __syncthreads();
    #pragma unroll
    for (int i = ty; i < 32; i += 8) {
        int e = e0 + i;
        if (e < E) g_xt[((size_t)b * E + e) * CIN + (c0 + tx)] = tile[tx][i];
    }
}

// ============================================================================
// Prep 2: split conv_w into hi/lo bf16 in k-major MMA layout
// ============================================================================
__global__ void wprep_kernel(const float* __restrict__ w) {
    int idx = blockIdx.x * 256 + threadIdx.x;         // over 256*128*5
    if (idx >= COUT * CIN * TAPS) return;
    int tap = idx % TAPS;
    int c   = (idx / TAPS) % CIN;
    int n   = idx / (TAPS * CIN);
    float v = w[idx];                                  // [n][c][0][tap]
    __nv_bfloat16 wh = __float2bfloat16(v);
    __nv_bfloat16 wl = __float2bfloat16(v - __bfloat162float(wh));
    int chalf = c >> 6, j = c & 63;
    int base = ((tap * 2 + chalf) * COUT + n) * 64 + j;
    g_w[base]                = wh;
    g_w[WPART_STRIDE + base] = wl;
}

// ============================================================================
// Main kernel: CTA = (batch, 128-edge tile). 512 threads, 16 warps (4m x 4n).
// Register acc D[128m x 256n]; per warp 32m x 64n = 64 fp32 regs/thread.
// ============================================================================
static constexpr int SMEM_BIAS = 0;            // 1 KB
static constexpr int SMEM_AH   = 1024;         // 16 KB  [128m][64k] bf16 SW128
static constexpr int SMEM_AL   = 1024 + 16384;
static constexpr int SMEM_BH   = 1024 + 2 * 16384;          // 32 KB [256n][64k]
static constexpr int SMEM_BL   = 1024 + 2 * 16384 + 32768;
static constexpr int SMEM_TOTAL = SMEM_BL + 32768;          // 99328 B

__global__ void __launch_bounds__(512, 1) mesh_main(
    const int* __restrict__ ne_idx,
    const float* __restrict__ bias,
    float* __restrict__ out)
{
    extern __shared__ char smem[];
    const uint32_t smem_base = smem_u32(smem);
    const int tid  = threadIdx.x;
    const int wid  = tid >> 5;
    const int lane = tid & 31;

    const int blk    = blockIdx.x;
    const int b      = blk / ETILES;
    const int et     = blk % ETILES;
    const int ebase  = et * ETILE;
    const int evalid = min(ETILE, E - ebase);

    if (tid < 256) ((float*)(smem + SMEM_BIAS))[tid] = bias[tid];

    const int warp_m = wid & 3;        // 0..3 -> m0 = 32*warp_m
    const int warp_n = wid >> 2;       // 0..3 -> n0 = 64*warp_n
    const int m0w = warp_m * 32;
    const int n0w = warp_n * 64;

    float acc[2][8][4];                // [m-tile 16][n-tile 8][frag]
    #pragma unroll
    for (int i = 0; i < 2; ++i)
        #pragma unroll
        for (int j = 0; j < 8; ++j)
            #pragma unroll
            for (int q = 0; q < 4; ++q) acc[i][j][q] = 0.f;

    const float* xtb = g_xt + (size_t)b * E * CIN;
    const int*   nb  = ne_idx + ((size_t)b * E + ebase) * 4;

    // Precompute ldmatrix lane-address components
    // A (x4): row = m + (lane & 15), col(k) = +8*(lane>>4)
    const int a_row = lane & 15;
    const int a_kof = (lane >> 4) << 3;
    // B (x4): row(n) = nb*16 + (lane&7) + ((lane&16)?8:0), col(k) = +8*((lane&8)?1:0)
    const int b_row = (lane & 7) + ((lane & 16) ? 8 : 0);
    const int b_kof = (lane & 8) ? 8 : 0;

    for (int it = 0; it < NSTAGES; ++it) {
        const int tap   = it >> 1;
        const int chalf = it & 1;
        const int c0    = chalf * 64;

        __syncthreads();   // previous stage's MMAs done reading smem

        // ---- Fill B tiles (Wh, Wl): swizzled copy from g_w ----
        {
            const uint4* srcH = (const uint4*)(g_w + (size_t)(tap * 2 + chalf) * COUT * 64);
            const uint4* srcL = (const uint4*)(g_w + WPART_STRIDE +
                                               (size_t)(tap * 2 + chalf) * COUT * 64);
            char* Bh = smem + SMEM_BH;
            char* Bl = smem + SMEM_BL;
            #pragma unroll
            for (int i = tid; i < 2048; i += 512) {     // 256 rows x 8 uint4
                int n  = i >> 3;
                int jq = i & 7;
                uint32_t off = SMEM_SWIZZLE_128B((uint32_t)(n * 128 + jq * 16));
                *(uint4*)(Bh + off) = srcH[i];
                *(uint4*)(Bl + off) = srcL[i];
            }
        }

        // ---- Fill A tiles (Gh, Gl): gather + combine + bf16 split ----
        {
            char* Ah = smem + SMEM_AH;
            char* Al = smem + SMEM_AL;
            const int g  = tid & 15;        // 16 threads per edge
            const int j0 = g * 4;           // 4 channels per thread
            #pragma unroll
            for (int pass = 0; pass < 4; ++pass) {
                const int m = pass * 32 + (tid >> 4);
                float v0 = 0.f, v1 = 0.f, v2 = 0.f, v3 = 0.f;
                if (m < evalid) {
                    if (tap == 0) {
                        const float4 a = *(const float4*)(xtb + (size_t)(ebase + m) * CIN + c0 + j0);
                        v0 = a.x; v1 = a.y; v2 = a.z; v3 = a.w;
                    } else {
                        const int4 nbr = *(const int4*)(nb + m * 4);
                        int ia, ib;
                        if (tap == 1 || tap == 3) { ia = nbr.x; ib = nbr.z; }
                        else                      { ia = nbr.y; ib = nbr.w; }
                        const float4 a = *(const float4*)(xtb + (size_t)ia * CIN + c0 + j0);
                        const float4 c = *(const float4*)(xtb + (size_t)ib * CIN + c0 + j0);
                        if (tap <= 2) {
                            v0 = a.x + c.x; v1 = a.y + c.y; v2 = a.z + c.z; v3 = a.w + c.w;
                        } else {
                            v0 = fabsf(a.x - c.x); v1 = fabsf(a.y - c.y);
                            v2 = fabsf(a.z - c.z); v3 = fabsf(a.w - c.w);
                        }
                    }
                }
                __nv_bfloat16 h0 = __float2bfloat16(v0);
                __nv_bfloat16 h1 = __float2bfloat16(v1);
                __nv_bfloat16 h2 = __float2bfloat16(v2);
                __nv_bfloat16 h3 = __float2bfloat16(v3);
                __nv_bfloat16 l0 = __float2bfloat16(v0 - __bfloat162float(h0));
                __nv_bfloat16 l1 = __float2bfloat16(v1 - __bfloat162float(h1));
                __nv_bfloat16 l2 = __float2bfloat16(v2 - __bfloat162float(h2));
                __nv_bfloat16 l3 = __float2bfloat16(v3 - __bfloat162float(h3));
                uint32_t off = SMEM_SWIZZLE_128B((uint32_t)(m * 128 + j0 * 2));
                *(uint2*)(Ah + off) = make_uint2(pack_bf16x2(h0, h1), pack_bf16x2(h2, h3));
                *(uint2*)(Al + off) = make_uint2(pack_bf16x2(l0, l1), pack_bf16x2(l2, l3));
            }
        }

        __syncthreads();

        // ---- Compute: 4 k16 steps x 3 split terms x 16 HMMA per warp ----
        #pragma unroll
        for (int kk = 0; kk < 4; ++kk) {
            const int kcol = kk * 16 + a_kof;   // for A addressing
            uint32_t ah[2][4], al[2][4], bf[8][2];

            // A hi/lo fragments (2 m-tiles each)
            #pragma unroll
            for (int mt = 0; mt < 2; ++mt) {
                const int row = m0w + mt * 16 + a_row;
                uint32_t off = SMEM_SWIZZLE_128B((uint32_t)(row * 128 + kcol * 2));
                ldsm_x4(ah[mt][0], ah[mt][1], ah[mt][2], ah[mt][3], smem_base + SMEM_AH + off);
                ldsm_x4(al[mt][0], al[mt][1], al[mt][2], al[mt][3], smem_base + SMEM_AL + off);
            }

            // B hi fragments (8 n-tiles via 4 x4-loads)
            #pragma unroll
            for (int nbq = 0; nbq < 4; ++nbq) {
                const int row = n0w + nbq * 16 + b_row;
                const int col = kk * 16 + b_kof;
                uint32_t off = SMEM_SWIZZLE_128B((uint32_t)(row * 128 + col * 2));
                ldsm_x4(bf[nbq * 2][0], bf[nbq * 2][1], bf[nbq * 2 + 1][0], bf[nbq * 2 + 1][1],
                        smem_base + SMEM_BH + off);
            }
            // term 1: Ah * Bh, term 3: Al * Bh
            #pragma unroll
            for (int mt = 0; mt < 2; ++mt)
                #pragma unroll
                for (int j = 0; j < 8; ++j) mma16816(acc[mt][j], ah[mt], bf[j]);
            #pragma unroll
            for (int mt = 0; mt < 2; ++mt)
                #pragma unroll
                for (int j = 0; j < 8; ++j) mma16816(acc[mt][j], al[mt], bf[j]);

            // B lo fragments reuse bf regs; term 2: Ah * Bl
            #pragma unroll
            for (int nbq = 0; nbq < 4; ++nbq) {
                const int row = n0w + nbq * 16 + b_row;
                const int col = kk * 16 + b_kof;
                uint32_t off = SMEM_SWIZZLE_128B((uint32_t)(row * 128 + col * 2));
                ldsm_x4(bf[nbq * 2][0], bf[nbq * 2][1], bf[nbq * 2 + 1][0], bf[nbq * 2 + 1][1],
                        smem_base + SMEM_BL + off);
            }
            #pragma unroll
            for (int mt = 0; mt < 2; ++mt)
                #pragma unroll
                for (int j = 0; j < 8; ++j) mma16816(acc[mt][j], ah[mt], bf[j]);
        }
    }

    // ---- Epilogue: +bias, scatter to out[b][o][e] ----
    {
        const float* bsm = (const float*)(smem + SMEM_BIAS);
        float* obase = out + (size_t)b * COUT * E;
        const int erow = ebase + m0w + (lane >> 2);
        #pragma unroll
        for (int mt = 0; mt < 2; ++mt) {
            const int e0g = erow + mt * 16;
            const bool v0 = (e0g     < E) && (m0w + mt * 16 + (lane >> 2)     < evalid + 0 + ebase - ebase);
            // simpler: row indices within tile
            const int r0 = m0w + mt * 16 + (lane >> 2);
            const int r1 = r0 + 8;
            const bool ok0 = r0 < evalid;
            const bool ok1 = r1 < evalid;
            #pragma unroll
            for (int j = 0; j < 8; ++j) {
                const int o = n0w + j * 8 + 2 * (lane & 3);
                const float b0 = bsm[o], b1 = bsm[o + 1];
                float* p0 = obase + (size_t)o * E;
                float* p1 = obase + (size_t)(o + 1) * E;
                if (ok0) {
                    p0[ebase + r0] = acc[mt][j][0] + b0;
                    p1[ebase + r0] = acc[mt][j][1] + b1;
                }
                if (ok1) {
                    p0[ebase + r1] = acc[mt][j][2] + b0;
                    p1[ebase + r1] = acc[mt][j][3] + b1;
                }
            }
        }
    }
}

// ============================================================================
// Launch
// ============================================================================
extern "C" void kernel_launch(void* const* d_in, const int* in_sizes, int n_in,
                              void* d_out, int out_size) {
    const float* x    = (const float*)d_in[0];
    const int*   ne   = (const int*)d_in[1];
    const float* w    = (const float*)d_in[2];
    const float* bias = (const float*)d_in[3];
    float*       out  = (float*)d_out;

    cudaFuncSetAttribute(mesh_main, cudaFuncAttributeMaxDynamicSharedMemorySize, SMEM_TOTAL);

    dim3 tgrid((E + 31) / 32, CIN / 32, BATCH);
    transpose_kernel<<<tgrid, dim3(32, 8)>>>(x);
    wprep_kernel<<<(COUT * CIN * TAPS + 255) / 256, 256>>>(w);
    mesh_main<<<NBLOCKS, 512, SMEM_TOTAL>>>(ne, bias, out);
}

// round 4
// speedup vs baseline: 1.1928x; 1.1928x over previous
#include <cuda_runtime.h>
#include <cuda_bf16.h>
#include <cstdint>

// ============================================================================
// out[b,o,e] = sum_{c,k} G[b,c,e,k] * W[o,c,k] + bias[o]
//   G taps: [self, n0+n2, n1+n3, |n0-n2|, |n1-n3|]
// GEMM [COUT=256] x [K'=640] x [B*E=120000], fp32 via 3-term bf16 split
// (GhWh + GhWl + GlWh). ldmatrix + mma.sync.m16n8k16 bf16 (tcgen05 rejected by
// ptxas on compute_103). Pipelined: cp.async W tiles, pre-issued gather LDGs,
// 3-slot A ring (sum-stage fill also produces the paired abs-stage tile).
// ============================================================================
static constexpr int BATCH = 4;
static constexpr int CIN   = 128;
static constexpr int COUT  = 256;
static constexpr int E     = 30000;
static constexpr int TAPS  = 5;

static constexpr int ETILE   = 128;
static constexpr int ETILES  = (E + ETILE - 1) / ETILE;   // 235
static constexpr int NBLOCKS = BATCH * ETILES;            // 940
static constexpr int NSTAGES = 10;

// Stage order (per chalf): tap sequence 0,1,3,2,4  (sum stage immediately
// precedes its paired abs stage, sharing gathered neighbor data)
// tap nibble table for pos 0..4 -> 0,1,3,2,4
#define STAGE_TAP(pos) ((int)((0x42310u >> ((pos) * 4)) & 0xF))

// ============================================================================
// Device scratch
// ============================================================================
__device__ float g_xt[(size_t)BATCH * E * CIN];            // x transposed [B,E,C]
__device__ __nv_bfloat16 g_w[2 * TAPS * 2 * COUT * 64];    // [part][tap][chalf][n][64]
static constexpr int WPART_STRIDE = TAPS * 2 * COUT * 64;  // 163840

// ============================================================================
// Helpers
// ============================================================================
__device__ __forceinline__ uint32_t smem_u32(const void* p) {
    uint32_t a;
    asm("{ .reg .u64 t; cvta.to.shared.u64 t, %1; cvt.u32.u64 %0, t; }"
        : "=r"(a) : "l"(p));
    return a;
}

#define SMEM_SWIZZLE_128B(off) ((off) ^ (((off) >> 3) & 0x70))

__device__ __forceinline__ void ldsm_x4(uint32_t& r0, uint32_t& r1,
                                        uint32_t& r2, uint32_t& r3, uint32_t addr) {
    asm volatile("ldmatrix.sync.aligned.m8n8.x4.shared.b16 {%0,%1,%2,%3}, [%4];"
                 : "=r"(r0), "=r"(r1), "=r"(r2), "=r"(r3) : "r"(addr));
}

__device__ __forceinline__ void mma16816(float* c, const uint32_t* a, const uint32_t* b) {
    asm volatile(
        "mma.sync.aligned.m16n8k16.row.col.f32.bf16.bf16.f32 "
        "{%0,%1,%2,%3}, {%4,%5,%6,%7}, {%8,%9}, {%0,%1,%2,%3};"
        : "+f"(c[0]), "+f"(c[1]), "+f"(c[2]), "+f"(c[3])
        : "r"(a[0]), "r"(a[1]), "r"(a[2]), "r"(a[3]), "r"(b[0]), "r"(b[1]));
}

__device__ __forceinline__ uint32_t pack_bf16x2(__nv_bfloat16 a, __nv_bfloat16 b) {
    return (uint32_t)__bfloat16_as_ushort(a) | ((uint32_t)__bfloat16_as_ushort(b) << 16);
}

__device__ __forceinline__ void cp_async16(uint32_t dst, const void* src) {
    asm volatile("cp.async.cg.shared.global [%0], [%1], 16;" :: "r"(dst), "l"(src));
}
#define CP_COMMIT() asm volatile("cp.async.commit_group;")
#define CP_WAIT0()  asm volatile("cp.async.wait_group 0;" ::: "memory")

// split 4 floats into hi/lo bf16 and store as two uint2
__device__ __forceinline__ void split_sts(float v0, float v1, float v2, float v3,
                                          char* dstH, char* dstL) {
    __nv_bfloat16 h0 = __float2bfloat16(v0), h1 = __float2bfloat16(v1);
    __nv_bfloat16 h2 = __float2bfloat16(v2), h3 = __float2bfloat16(v3);
    __nv_bfloat16 l0 = __float2bfloat16(v0 - __bfloat162float(h0));
    __nv_bfloat16 l1 = __float2bfloat16(v1 - __bfloat162float(h1));
    __nv_bfloat16 l2 = __float2bfloat16(v2 - __bfloat162float(h2));
    __nv_bfloat16 l3 = __float2bfloat16(v3 - __bfloat162float(h3));
    *(uint2*)dstH = make_uint2(pack_bf16x2(h0, h1), pack_bf16x2(h2, h3));
    *(uint2*)dstL = make_uint2(pack_bf16x2(l0, l1), pack_bf16x2(l2, l3));
}

// ============================================================================
// Prep 1: transpose x [B,C,E] -> g_xt [B,E,C]
// ============================================================================
__global__ void transpose_kernel(const float* __restrict__ x) {
    __shared__ float tile[32][33];
    int b  = blockIdx.z;
    int c0 = blockIdx.y * 32;
    int e0 = blockIdx.x * 32;
    int tx = threadIdx.x, ty = threadIdx.y;

    #pragma unroll
    for (int i = ty; i < 32; i += 8) {
        int e = e0 + tx;
        float v = 0.f;
        if (e < E) v = x[((size_t)b * CIN + (c0 + i)) * E + e];
        tile[i][tx] = v;
    }
    __syncthreads();
    #pragma unroll
    for (int i = ty; i < 32; i += 8) {
        int e = e0 + i;
        if (e < E) g_xt[((size_t)b * E + e) * CIN + (c0 + tx)] = tile[tx][i];
    }
}

// ============================================================================
// Prep 2: split conv_w into hi/lo bf16, k-major MMA layout
// ============================================================================
__global__ void wprep_kernel(const float* __restrict__ w) {
    int idx = blockIdx.x * 256 + threadIdx.x;
    if (idx >= COUT * CIN * TAPS) return;
    int tap = idx % TAPS;
    int c   = (idx / TAPS) % CIN;
    int n   = idx / (TAPS * CIN);
    float v = w[idx];
    __nv_bfloat16 wh = __float2bfloat16(v);
    __nv_bfloat16 wl = __float2bfloat16(v - __bfloat162float(wh));
    int chalf = c >> 6, j = c & 63;
    int base = ((tap * 2 + chalf) * COUT + n) * 64 + j;
    g_w[base]                = wh;
    g_w[WPART_STRIDE + base] = wl;
}

// ============================================================================
// Main kernel
// ============================================================================
static constexpr int SMEM_BIAS = 0;                // 1 KB
static constexpr int SMEM_A    = 1024;             // 3 slots x (Ah,Al) x 16KB = 96KB
static constexpr int SMEM_B    = 1024 + 3 * 32768; // 2 bufs x (Bh,Bl) x 32KB = 128KB
static constexpr int SMEM_TOTAL = SMEM_B + 2 * 65536;   // 230400 B

#define A_H(slot) (SMEM_A + (slot) * 32768)
#define A_L(slot) (SMEM_A + (slot) * 32768 + 16384)
#define B_H(buf)  (SMEM_B + (buf) * 65536)
#define B_L(buf)  (SMEM_B + (buf) * 65536 + 32768)

__global__ void __launch_bounds__(512, 1) mesh_main(
    const int* __restrict__ ne_idx,
    const float* __restrict__ bias,
    float* __restrict__ out)
{
    extern __shared__ char smem[];
    const uint32_t smem_base = smem_u32(smem);
    const int tid  = threadIdx.x;
    const int wid  = tid >> 5;
    const int lane = tid & 31;

    const int blk    = blockIdx.x;
    const int b      = blk / ETILES;
    const int et     = blk % ETILES;
    const int ebase  = et * ETILE;
    const int evalid = min(ETILE, E - ebase);

    if (tid < 256) ((float*)(smem + SMEM_BIAS))[tid] = bias[tid];

    const int warp_m = wid & 3;
    const int warp_n = wid >> 2;
    const int m0w = warp_m * 32;
    const int n0w = warp_n * 64;

    float acc[2][8][4];
    #pragma unroll
    for (int i = 0; i < 2; ++i)
        #pragma unroll
        for (int j = 0; j < 8; ++j)
            #pragma unroll
            for (int q = 0; q < 4; ++q) acc[i][j][q] = 0.f;

    const float* xtb = g_xt + (size_t)b * E * CIN;
    const int*   nb  = ne_idx + ((size_t)b * E + ebase) * 4;

    // ldmatrix lane addressing
    const int a_row = lane & 15;
    const int a_kof = (lane >> 4) << 3;
    const int b_row = (lane & 7) + ((lane & 16) ? 8 : 0);
    const int b_kof = (lane & 8) ? 8 : 0;

    // gather fill lane mapping: 16 threads/edge, 4 channels/thread
    const int gj0 = (tid & 15) * 4;
    const int gm0 = tid >> 4;          // +32 per pass

    // ---------------- Prologue: stage 0 = (tap0, chalf0) ----------------
    {
        // B buf0 via cp.async
        const __nv_bfloat16* srcH = g_w;                 // widx 0
        const __nv_bfloat16* srcL = g_w + WPART_STRIDE;
        #pragma unroll
        for (int q = 0; q < 4; ++q) {
            int i = tid + q * 512;
            uint32_t off = SMEM_SWIZZLE_128B((uint32_t)((i >> 3) * 128 + (i & 7) * 16));
            cp_async16(smem_base + B_H(0) + off, (const char*)srcH + i * 16);
            cp_async16(smem_base + B_L(0) + off, (const char*)srcL + i * 16);
        }
        CP_COMMIT();
        // A slot0: self gather, chalf 0
        #pragma unroll
        for (int pass = 0; pass < 4; ++pass) {
            const int m = pass * 32 + gm0;
            float4 a = make_float4(0.f, 0.f, 0.f, 0.f);
            if (m < evalid)
                a = *(const float4*)(xtb + (size_t)(ebase + m) * CIN + gj0);
            uint32_t off = SMEM_SWIZZLE_128B((uint32_t)(m * 128 + gj0 * 2));
            split_sts(a.x, a.y, a.z, a.w, smem + A_H(0) + off, smem + A_L(0) + off);
        }
        CP_WAIT0();
        __syncthreads();
    }

    // ---------------- Main pipeline ----------------
    for (int s = 0; s < NSTAGES; ++s) {
        const int as  = s % 3;
        const int buf = s & 1;
        const int nxt = s + 1;

        // Next-stage metadata
        int fkind = 0;            // 0 none, 1 self, 2 pair(sum+abs)
        int n_tap = 0, n_c0 = 0, slotS = 0, slotA = 0;
        if (nxt < NSTAGES) {
            const int npos = (nxt < 5) ? nxt : nxt - 5;
            n_tap = STAGE_TAP(npos);
            n_c0  = (nxt >= 5) ? 64 : 0;
            slotS = nxt % 3;
            slotA = (s + 2) % 3;
            if (n_tap == 0) fkind = 1;
            else if (n_tap == 1 || n_tap == 2) fkind = 2;

            // B fill for next stage (always) via cp.async
            const int widx = n_tap * 2 + ((nxt >= 5) ? 1 : 0);
            const __nv_bfloat16* srcH = g_w + (size_t)widx * COUT * 64;
            const __nv_bfloat16* srcL = srcH + WPART_STRIDE;
            const uint32_t dH = smem_base + B_H(buf ^ 1);
            const uint32_t dL = smem_base + B_L(buf ^ 1);
            #pragma unroll
            for (int q = 0; q < 4; ++q) {
                int i = tid + q * 512;
                uint32_t off = SMEM_SWIZZLE_128B((uint32_t)((i >> 3) * 128 + (i & 7) * 16));
                cp_async16(dH + off, (const char*)srcH + i * 16);
                cp_async16(dL + off, (const char*)srcL + i * 16);
            }
            CP_COMMIT();
        }

        const uint32_t aBH = smem_base + A_H(as);
        const uint32_t aBL = smem_base + A_L(as);
        const uint32_t bBH = smem_base + B_H(buf);
        const uint32_t bBL = smem_base + B_L(buf);

        #pragma unroll
        for (int kk = 0; kk < 4; ++kk) {
            // ---- issue gather LDGs for next stage, pass kk ----
            float4 ga = make_float4(0.f, 0.f, 0.f, 0.f);
            float4 gc = make_float4(0.f, 0.f, 0.f, 0.f);
            const int gm = kk * 32 + gm0;
            if (fkind == 1) {
                if (gm < evalid)
                    ga = *(const float4*)(xtb + (size_t)(ebase + gm) * CIN + n_c0 + gj0);
            } else if (fkind == 2) {
                if (gm < evalid) {
                    const int4 nbr = *(const int4*)(nb + gm * 4);
                    const int ia = (n_tap == 1) ? nbr.x : nbr.y;
                    const int ib = (n_tap == 1) ? nbr.z : nbr.w;
                    ga = *(const float4*)(xtb + (size_t)ia * CIN + n_c0 + gj0);
                    gc = *(const float4*)(xtb + (size_t)ib * CIN + n_c0 + gj0);
                }
            }

            // ---- compute chunk kk: 3 terms x 16 HMMA ----
            {
                const int kcol = kk * 16 + a_kof;
                uint32_t ah[2][4], al[2][4], bf[8][2];
                #pragma unroll
                for (int mt = 0; mt < 2; ++mt) {
                    const int row = m0w + mt * 16 + a_row;
                    uint32_t off = SMEM_SWIZZLE_128B((uint32_t)(row * 128 + kcol * 2));
                    ldsm_x4(ah[mt][0], ah[mt][1], ah[mt][2], ah[mt][3], aBH + off);
                    ldsm_x4(al[mt][0], al[mt][1], al[mt][2], al[mt][3], aBL + off);
                }
                #pragma unroll
                for (int nbq = 0; nbq < 4; ++nbq) {
                    const int row = n0w + nbq * 16 + b_row;
                    uint32_t off = SMEM_SWIZZLE_128B((uint32_t)(row * 128 + (kk * 16 + b_kof) * 2));
                    ldsm_x4(bf[nbq * 2][0], bf[nbq * 2][1],
                            bf[nbq * 2 + 1][0], bf[nbq * 2 + 1][1], bBH + off);
                }
                #pragma unroll
                for (int mt = 0; mt < 2; ++mt)
                    #pragma unroll
                    for (int j = 0; j < 8; ++j) mma16816(acc[mt][j], ah[mt], bf[j]);
                #pragma unroll
                for (int mt = 0; mt < 2; ++mt)
                    #pragma unroll
                    for (int j = 0; j < 8; ++j) mma16816(acc[mt][j], al[mt], bf[j]);
                #pragma unroll
                for (int nbq = 0; nbq < 4; ++nbq) {
                    const int row = n0w + nbq * 16 + b_row;
                    uint32_t off = SMEM_SWIZZLE_128B((uint32_t)(row * 128 + (kk * 16 + b_kof) * 2));
                    ldsm_x4(bf[nbq * 2][0], bf[nbq * 2][1],
                            bf[nbq * 2 + 1][0], bf[nbq * 2 + 1][1], bBL + off);
                }
                #pragma unroll
                for (int mt = 0; mt < 2; ++mt)
                    #pragma unroll
                    for (int j = 0; j < 8; ++j) mma16816(acc[mt][j], ah[mt], bf[j]);
            }

            // ---- convert + STS for next stage, pass kk ----
            if (fkind == 1) {
                uint32_t off = SMEM_SWIZZLE_128B((uint32_t)(gm * 128 + gj0 * 2));
                split_sts(ga.x, ga.y, ga.z, ga.w,
                          smem + A_H(slotS) + off, smem + A_L(slotS) + off);
            } else if (fkind == 2) {
                uint32_t off = SMEM_SWIZZLE_128B((uint32_t)(gm * 128 + gj0 * 2));
                split_sts(ga.x + gc.x, ga.y + gc.y, ga.z + gc.z, ga.w + gc.w,
                          smem + A_H(slotS) + off, smem + A_L(slotS) + off);
                split_sts(fabsf(ga.x - gc.x), fabsf(ga.y - gc.y),
                          fabsf(ga.z - gc.z), fabsf(ga.w - gc.w),
                          smem + A_H(slotA) + off, smem + A_L(slotA) + off);
            }
        }

        if (nxt < NSTAGES) CP_WAIT0();
        __syncthreads();
    }

    // ---------------- Epilogue: +bias, store out[b][o][e] ----------------
    {
        const float* bsm = (const float*)(smem + SMEM_BIAS);
        float* obase = out + (size_t)b * COUT * E;
        #pragma unroll
        for (int mt = 0; mt < 2; ++mt) {
            const int r0 = m0w + mt * 16 + (lane >> 2);
            const int r1 = r0 + 8;
            const bool ok0 = r0 < evalid;
            const bool ok1 = r1 < evalid;
            #pragma unroll
            for (int j = 0; j < 8; ++j) {
                const int o = n0w + j * 8 + 2 * (lane & 3);
                const float b0 = bsm[o], b1 = bsm[o + 1];
                float* p0 = obase + (size_t)o * E;
                float* p1 = obase + (size_t)(o + 1) * E;
                if (ok0) {
                    p0[ebase + r0] = acc[mt][j][0] + b0;
                    p1[ebase + r0] = acc[mt][j][1] + b1;
                }
                if (ok1) {
                    p0[ebase + r1] = acc[mt][j][2] + b0;
                    p1[ebase + r1] = acc[mt][j][3] + b1;
                }
            }
        }
    }
}

// ============================================================================
// Launch
// ============================================================================
extern "C" void kernel_launch(void* const* d_in, const int* in_sizes, int n_in,
                              void* d_out, int out_size) {
    const float* x    = (const float*)d_in[0];
    const int*   ne   = (const int*)d_in[1];
    const float* w    = (const float*)d_in[2];
    const float* bias = (const float*)d_in[3];
    float*       out  = (float*)d_out;

    cudaFuncSetAttribute(mesh_main, cudaFuncAttributeMaxDynamicSharedMemorySize, SMEM_TOTAL);

    dim3 tgrid((E + 31) / 32, CIN / 32, BATCH);
    transpose_kernel<<<tgrid, dim3(32, 8)>>>(x);
    wprep_kernel<<<(COUT * CIN * TAPS + 255) / 256, 256>>>(w);
    mesh_main<<<NBLOCKS, 512, SMEM_TOTAL>>>(ne, bias, out);
}

// round 5
// speedup vs baseline: 1.7233x; 1.4448x over previous
#include <cuda_runtime.h>
#include <cuda_fp16.h>
#include <cstdint>

// ============================================================================
// out[b,o,e] = sum_{c,k} G[b,c,e,k] * W[o,c,k] + bias[o]
//   G taps: [self, n0+n2, n1+n3, |n0-n2|, |n1-n3|]
// GEMM [COUT=256] x [K'=640] x [B*E=120000].
// Precision: fp16 2-term split. A = fp16(G) (single), W = Wh + Wl (fp16 pair,
// residual 2^-22). Output rel err ~2e-4 << 1e-3 gate.
// ldmatrix + mma.sync.m16n8k16.f16 (tcgen05 rejected by ptxas on compute_103).
// Pipelined: cp.async W tiles (double buffer), gather LDGs prefetched one
// k-chunk ahead, 3-slot A ring (sum stage also fills paired abs stage).
// ============================================================================
static constexpr int BATCH = 4;
static constexpr int CIN   = 128;
static constexpr int COUT  = 256;
static constexpr int E     = 30000;
static constexpr int TAPS  = 5;

static constexpr int ETILE   = 128;
static constexpr int ETILES  = (E + ETILE - 1) / ETILE;   // 235
static constexpr int NBLOCKS = BATCH * ETILES;            // 940
static constexpr int NSTAGES = 10;

// Stage order per chalf: taps 0,1,3,2,4 (sum stage directly precedes its
// paired abs stage; both filled from one set of gathers)
#define STAGE_TAP(pos) ((int)((0x42310u >> ((pos) * 4)) & 0xF))

// ============================================================================
// Device scratch
// ============================================================================
__device__ float g_xt[(size_t)BATCH * E * CIN];      // x transposed [B,E,C]
__device__ __half g_w[2 * TAPS * 2 * COUT * 64];     // [part][tap][chalf][n][64]
static constexpr int WPART_STRIDE = TAPS * 2 * COUT * 64;  // 163840

// ============================================================================
// Helpers
// ============================================================================
__device__ __forceinline__ uint32_t smem_u32(const void* p) {
    uint32_t a;
    asm("{ .reg .u64 t; cvta.to.shared.u64 t, %1; cvt.u32.u64 %0, t; }"
        : "=r"(a) : "l"(p));
    return a;
}

#define SMEM_SWIZZLE_128B(off) ((off) ^ (((off) >> 3) & 0x70))

__device__ __forceinline__ void ldsm_x4(uint32_t& r0, uint32_t& r1,
                                        uint32_t& r2, uint32_t& r3, uint32_t addr) {
    asm volatile("ldmatrix.sync.aligned.m8n8.x4.shared.b16 {%0,%1,%2,%3}, [%4];"
                 : "=r"(r0), "=r"(r1), "=r"(r2), "=r"(r3) : "r"(addr));
}

__device__ __forceinline__ void mma16816(float* c, const uint32_t* a, const uint32_t* b) {
    asm volatile(
        "mma.sync.aligned.m16n8k16.row.col.f32.f16.f16.f32 "
        "{%0,%1,%2,%3}, {%4,%5,%6,%7}, {%8,%9}, {%0,%1,%2,%3};"
        : "+f"(c[0]), "+f"(c[1]), "+f"(c[2]), "+f"(c[3])
        : "r"(a[0]), "r"(a[1]), "r"(a[2]), "r"(a[3]), "r"(b[0]), "r"(b[1]));
}

__device__ __forceinline__ uint32_t pack_half2(float a, float b) {
    __half2 h = __floats2half2_rn(a, b);
    return *(uint32_t*)&h;
}

__device__ __forceinline__ void cp_async16(uint32_t dst, const void* src) {
    asm volatile("cp.async.cg.shared.global [%0], [%1], 16;" :: "r"(dst), "l"(src));
}
#define CP_COMMIT() asm volatile("cp.async.commit_group;")
#define CP_WAIT0()  asm volatile("cp.async.wait_group 0;" ::: "memory")

// ============================================================================
// Prep 1: transpose x [B,C,E] -> g_xt [B,E,C]. 128e x 32c tiles, float4 I/O.
// ============================================================================
__global__ void transpose_kernel(const float* __restrict__ x) {
    __shared__ float tile[32 * 132];          // [c][e], row stride 132 floats
    const int b  = blockIdx.z;
    const int c0 = blockIdx.y * 32;
    const int e0 = blockIdx.x * 128;
    const int tid = threadIdx.x;              // 256

    // Read: 32 c-rows x 32 float4 along e (coalesced LDG.128 + STS.128)
    #pragma unroll
    for (int i = 0; i < 4; ++i) {
        const int idx = tid + i * 256;
        const int c = idx >> 5;
        const int q = idx & 31;
        const int e = e0 + q * 4;
        float4 v = make_float4(0.f, 0.f, 0.f, 0.f);
        if (e < E)   // E % 4 == 0, so float4 at e<E is fully in-bounds
            v = *(const float4*)(x + ((size_t)b * CIN + c0 + c) * E + e);
        *(float4*)(tile + c * 132 + q * 4) = v;
    }
    __syncthreads();

    // Write: 128 e-rows x 8 float4 along c (scalar LDS + coalesced STG.128)
    #pragma unroll
    for (int i = 0; i < 4; ++i) {
        const int idx = tid + i * 256;
        const int e = idx >> 3;
        const int m = idx & 7;
        const int c = m * 4;
        if (e0 + e < E) {
            float4 v;
            v.x = tile[(c + 0) * 132 + e];
            v.y = tile[(c + 1) * 132 + e];
            v.z = tile[(c + 2) * 132 + e];
            v.w = tile[(c + 3) * 132 + e];
            *(float4*)(g_xt + ((size_t)b * E + e0 + e) * CIN + c0 + c) = v;
        }
    }
}

// ============================================================================
// Prep 2: split conv_w into hi/lo fp16, k-major MMA layout
// ============================================================================
__global__ void wprep_kernel(const float* __restrict__ w) {
    int idx = blockIdx.x * 256 + threadIdx.x;
    if (idx >= COUT * CIN * TAPS) return;
    int tap = idx % TAPS;
    int c   = (idx / TAPS) % CIN;
    int n   = idx / (TAPS * CIN);
    float v = w[idx];
    __half wh = __float2half_rn(v);
    __half wl = __float2half_rn(v - __half2float(wh));
    int chalf = c >> 6, j = c & 63;
    int base = ((tap * 2 + chalf) * COUT + n) * 64 + j;
    g_w[base]                = wh;
    g_w[WPART_STRIDE + base] = wl;
}

// ============================================================================
// Main kernel
// ============================================================================
static constexpr int SMEM_BIAS = 0;                 // 1 KB
static constexpr int SMEM_A    = 1024;              // 3 slots x 16KB = 48KB
static constexpr int SMEM_B    = 1024 + 3 * 16384;  // 2 bufs x (Bh,Bl) x 32KB
static constexpr int SMEM_TOTAL = SMEM_B + 2 * 65536;   // 181248 B

#define A_H(slot) (SMEM_A + (slot) * 16384)
#define B_H(buf)  (SMEM_B + (buf) * 65536)
#define B_L(buf)  (SMEM_B + (buf) * 65536 + 32768)

__global__ void __launch_bounds__(512, 1) mesh_main(
    const int* __restrict__ ne_idx,
    const float* __restrict__ bias,
    float* __restrict__ out)
{
    extern __shared__ char smem[];
    const uint32_t smem_base = smem_u32(smem);
    const int tid  = threadIdx.x;
    const int wid  = tid >> 5;
    const int lane = tid & 31;

    const int blk    = blockIdx.x;
    const int b      = blk / ETILES;
    const int et     = blk % ETILES;
    const int ebase  = et * ETILE;
    const int evalid = min(ETILE, E - ebase);

    if (tid < 256) ((float*)(smem + SMEM_BIAS))[tid] = bias[tid];

    const int warp_m = wid & 3;
    const int warp_n = wid >> 2;
    const int m0w = warp_m * 32;
    const int n0w = warp_n * 64;

    float acc[2][8][4];
    #pragma unroll
    for (int i = 0; i < 2; ++i)
        #pragma unroll
        for (int j = 0; j < 8; ++j)
            #pragma unroll
            for (int q = 0; q < 4; ++q) acc[i][j][q] = 0.f;

    const float* xtb = g_xt + (size_t)b * E * CIN;
    const int*   nb  = ne_idx + ((size_t)b * E + ebase) * 4;

    // ldmatrix lane addressing
    const int a_row = lane & 15;
    const int a_kof = (lane >> 4) << 3;
    const int b_row = (lane & 7) + ((lane & 16) ? 8 : 0);
    const int b_kof = (lane & 8) ? 8 : 0;

    // gather fill mapping: 16 threads/edge, 4 channels/thread
    const int gj0 = (tid & 15) * 4;
    const int gm0 = tid >> 4;

    // ---------------- Prologue: stage 0 = (tap0, chalf0) ----------------
    {
        const __half* srcH = g_w;
        const __half* srcL = g_w + WPART_STRIDE;
        #pragma unroll
        for (int q = 0; q < 4; ++q) {
            int i = tid + q * 512;
            uint32_t off = SMEM_SWIZZLE_128B((uint32_t)((i >> 3) * 128 + (i & 7) * 16));
            cp_async16(smem_base + B_H(0) + off, (const char*)srcH + i * 16);
            cp_async16(smem_base + B_L(0) + off, (const char*)srcL + i * 16);
        }
        CP_COMMIT();
        #pragma unroll
        for (int pass = 0; pass < 4; ++pass) {
            const int m = pass * 32 + gm0;
            float4 a = make_float4(0.f, 0.f, 0.f, 0.f);
            if (m < evalid)
                a = *(const float4*)(xtb + (size_t)(ebase + m) * CIN + gj0);
            uint32_t off = SMEM_SWIZZLE_128B((uint32_t)(m * 128 + gj0 * 2));
            *(uint2*)(smem + A_H(0) + off) =
                make_uint2(pack_half2(a.x, a.y), pack_half2(a.z, a.w));
        }
        CP_WAIT0();
        __syncthreads();
    }

    // ---------------- Main pipeline ----------------
    for (int s = 0; s < NSTAGES; ++s) {
        const int as  = s % 3;
        const int buf = s & 1;
        const int nxt = s + 1;

        int fkind = 0;            // 0 none, 1 self, 2 pair(sum+abs)
        int n_tap = 0, n_c0 = 0, slotS = 0, slotA = 0;
        if (nxt < NSTAGES) {
            const int npos = (nxt < 5) ? nxt : nxt - 5;
            n_tap = STAGE_TAP(npos);
            n_c0  = (nxt >= 5) ? 64 : 0;
            slotS = nxt % 3;
            slotA = (s + 2) % 3;
            if (n_tap == 0) fkind = 1;
            else if (n_tap == 1 || n_tap == 2) fkind = 2;

            // B fill for next stage via cp.async
            const int widx = n_tap * 2 + ((nxt >= 5) ? 1 : 0);
            const __half* srcH = g_w + (size_t)widx * COUT * 64;
            const __half* srcL = srcH + WPART_STRIDE;
            const uint32_t dH = smem_base + B_H(buf ^ 1);
            const uint32_t dL = smem_base + B_L(buf ^ 1);
            #pragma unroll
            for (int q = 0; q < 4; ++q) {
                int i = tid + q * 512;
                uint32_t off = SMEM_SWIZZLE_128B((uint32_t)((i >> 3) * 128 + (i & 7) * 16));
                cp_async16(dH + off, (const char*)srcH + i * 16);
                cp_async16(dL + off, (const char*)srcL + i * 16);
            }
            CP_COMMIT();
        }

        const uint32_t aBH = smem_base + A_H(as);
        const uint32_t bBH = smem_base + B_H(buf);
        const uint32_t bBL = smem_base + B_L(buf);

        // gather prefetch for pass 0
        float4 ga = make_float4(0.f, 0.f, 0.f, 0.f);
        float4 gc = make_float4(0.f, 0.f, 0.f, 0.f);
        if (fkind == 1) {
            if (gm0 < evalid)
                ga = *(const float4*)(xtb + (size_t)(ebase + gm0) * CIN + n_c0 + gj0);
        } else if (fkind == 2) {
            if (gm0 < evalid) {
                const int4 nbr = *(const int4*)(nb + gm0 * 4);
                const int ia = (n_tap == 1) ? nbr.x : nbr.y;
                const int ib = (n_tap == 1) ? nbr.z : nbr.w;
                ga = *(const float4*)(xtb + (size_t)ia * CIN + n_c0 + gj0);
                gc = *(const float4*)(xtb + (size_t)ib * CIN + n_c0 + gj0);
            }
        }

        #pragma unroll
        for (int kk = 0; kk < 4; ++kk) {
            // issue gather for pass kk+1 (latency hidden under MMAs below)
            float4 gan = make_float4(0.f, 0.f, 0.f, 0.f);
            float4 gcn = make_float4(0.f, 0.f, 0.f, 0.f);
            if (kk < 3) {
                const int gm = (kk + 1) * 32 + gm0;
                if (fkind == 1) {
                    if (gm < evalid)
                        gan = *(const float4*)(xtb + (size_t)(ebase + gm) * CIN + n_c0 + gj0);
                } else if (fkind == 2) {
                    if (gm < evalid) {
                        const int4 nbr = *(const int4*)(nb + gm * 4);
                        const int ia = (n_tap == 1) ? nbr.x : nbr.y;
                        const int ib = (n_tap == 1) ? nbr.z : nbr.w;
                        gan = *(const float4*)(xtb + (size_t)ia * CIN + n_c0 + gj0);
                        gcn = *(const float4*)(xtb + (size_t)ib * CIN + n_c0 + gj0);
                    }
                }
            }

            // ---- compute chunk kk: 2 terms x 16 HMMA ----
            {
                const int kcol = kk * 16 + a_kof;
                uint32_t ah[2][4], bf[8][2];
                #pragma unroll
                for (int mt = 0; mt < 2; ++mt) {
                    const int row = m0w + mt * 16 + a_row;
                    uint32_t off = SMEM_SWIZZLE_128B((uint32_t)(row * 128 + kcol * 2));
                    ldsm_x4(ah[mt][0], ah[mt][1], ah[mt][2], ah[mt][3], aBH + off);
                }
                #pragma unroll
                for (int nbq = 0; nbq < 4; ++nbq) {
                    const int row = n0w + nbq * 16 + b_row;
                    uint32_t off = SMEM_SWIZZLE_128B((uint32_t)(row * 128 + (kk * 16 + b_kof) * 2));
                    ldsm_x4(bf[nbq * 2][0], bf[nbq * 2][1],
                            bf[nbq * 2 + 1][0], bf[nbq * 2 + 1][1], bBH + off);
                }
                #pragma unroll
                for (int mt = 0; mt < 2; ++mt)
                    #pragma unroll
                    for (int j = 0; j < 8; ++j) mma16816(acc[mt][j], ah[mt], bf[j]);
                #pragma unroll
                for (int nbq = 0; nbq < 4; ++nbq) {
                    const int row = n0w + nbq * 16 + b_row;
                    uint32_t off = SMEM_SWIZZLE_128B((uint32_t)(row * 128 + (kk * 16 + b_kof) * 2));
                    ldsm_x4(bf[nbq * 2][0], bf[nbq * 2][1],
                            bf[nbq * 2 + 1][0], bf[nbq * 2 + 1][1], bBL + off);
                }
                #pragma unroll
                for (int mt = 0; mt < 2; ++mt)
                    #pragma unroll
                    for (int j = 0; j < 8; ++j) mma16816(acc[mt][j], ah[mt], bf[j]);
            }

            // ---- convert + STS for pass kk ----
            {
                const int gm = kk * 32 + gm0;
                uint32_t off = SMEM_SWIZZLE_128B((uint32_t)(gm * 128 + gj0 * 2));
                if (fkind == 1) {
                    *(uint2*)(smem + A_H(slotS) + off) =
                        make_uint2(pack_half2(ga.x, ga.y), pack_half2(ga.z, ga.w));
                } else if (fkind == 2) {
                    *(uint2*)(smem + A_H(slotS) + off) =
                        make_uint2(pack_half2(ga.x + gc.x, ga.y + gc.y),
                                   pack_half2(ga.z + gc.z, ga.w + gc.w));
                    *(uint2*)(smem + A_H(slotA) + off) =
                        make_uint2(pack_half2(fabsf(ga.x - gc.x), fabsf(ga.y - gc.y)),
                                   pack_half2(fabsf(ga.z - gc.z), fabsf(ga.w - gc.w)));
                }
            }
            ga = gan; gc = gcn;
        }

        if (nxt < NSTAGES) CP_WAIT0();
        __syncthreads();
    }

    // ---------------- Epilogue: +bias, store out[b][o][e] ----------------
    {
        const float* bsm = (const float*)(smem + SMEM_BIAS);
        float* obase = out + (size_t)b * COUT * E;
        #pragma unroll
        for (int mt = 0; mt < 2; ++mt) {
            const int r0 = m0w + mt * 16 + (lane >> 2);
            const int r1 = r0 + 8;
            const bool ok0 = r0 < evalid;
            const bool ok1 = r1 < evalid;
            #pragma unroll
            for (int j = 0; j < 8; ++j) {
                const int o = n0w + j * 8 + 2 * (lane & 3);
                const float b0 = bsm[o], b1 = bsm[o + 1];
                float* p0 = obase + (size_t)o * E;
                float* p1 = obase + (size_t)(o + 1) * E;
                if (ok0) {
                    p0[ebase + r0] = acc[mt][j][0] + b0;
                    p1[ebase + r0] = acc[mt][j][1] + b1;
                }
                if (ok1) {
                    p0[ebase + r1] = acc[mt][j][2] + b0;
                    p1[ebase + r1] = acc[mt][j][3] + b1;
                }
            }
        }
    }
}

// ============================================================================
// Launch
// ============================================================================
extern "C" void kernel_launch(void* const* d_in, const int* in_sizes, int n_in,
                              void* d_out, int out_size) {
    const float* x    = (const float*)d_in[0];
    const int*   ne   = (const int*)d_in[1];
    const float* w    = (const float*)d_in[2];
    const float* bias = (const float*)d_in[3];
    float*       out  = (float*)d_out;

    cudaFuncSetAttribute(mesh_main, cudaFuncAttributeMaxDynamicSharedMemorySize, SMEM_TOTAL);

    dim3 tgrid((E + 127) / 128, CIN / 32, BATCH);
    transpose_kernel<<<tgrid, 256>>>(x);
    wprep_kernel<<<(COUT * CIN * TAPS + 255) / 256, 256>>>(w);
    mesh_main<<<NBLOCKS, 512, SMEM_TOTAL>>>(ne, bias, out);
}

// round 6
// speedup vs baseline: 2.2902x; 1.3290x over previous
#include <cuda_runtime.h>
#include <cuda_fp16.h>
#include <cstdint>

// ============================================================================
// out[b,o,e] = sum_{c,k} G[b,c,e,k] * W[o,c,k] + bias[o]
//   G taps: [self, n0+n2, n1+n3, |n0-n2|, |n1-n3|]
// GEMM [COUT=256] x [K'=640] x [B*E=120000].
// Precision: single fp16 on BOTH operands (G fp16, W fp16). Independent
// quantization errors ~2.4e-4 each -> output rel_err ~3e-4 << 1e-3 gate.
// ldmatrix + mma.sync.m16n8k16.f16 (tcgen05 rejected by ptxas on compute_103).
// Pipelined: cp.async W tiles (double buffer), gather LDGs prefetched one
// k-chunk ahead, 3-slot A ring (sum stage also fills paired abs stage).
// ============================================================================
static constexpr int BATCH = 4;
static constexpr int CIN   = 128;
static constexpr int COUT  = 256;
static constexpr int E     = 30000;
static constexpr int TAPS  = 5;

static constexpr int ETILE   = 128;
static constexpr int ETILES  = (E + ETILE - 1) / ETILE;   // 235
static constexpr int NBLOCKS = BATCH * ETILES;            // 940
static constexpr int NSTAGES = 10;

// Stage order per chalf: taps 0,1,3,2,4 (sum stage directly precedes its
// paired abs stage; both filled from one set of gathers)
#define STAGE_TAP(pos) ((int)((0x42310u >> ((pos) * 4)) & 0xF))

// ============================================================================
// Device scratch
// ============================================================================
__device__ float g_xt[(size_t)BATCH * E * CIN];      // x transposed [B,E,C]
__device__ __half g_w[TAPS * 2 * COUT * 64];         // [tap][chalf][n][64]

// ============================================================================
// Helpers
// ============================================================================
__device__ __forceinline__ uint32_t smem_u32(const void* p) {
    uint32_t a;
    asm("{ .reg .u64 t; cvta.to.shared.u64 t, %1; cvt.u32.u64 %0, t; }"
        : "=r"(a) : "l"(p));
    return a;
}

#define SMEM_SWIZZLE_128B(off) ((off) ^ (((off) >> 3) & 0x70))

__device__ __forceinline__ void ldsm_x4(uint32_t& r0, uint32_t& r1,
                                        uint32_t& r2, uint32_t& r3, uint32_t addr) {
    asm volatile("ldmatrix.sync.aligned.m8n8.x4.shared.b16 {%0,%1,%2,%3}, [%4];"
                 : "=r"(r0), "=r"(r1), "=r"(r2), "=r"(r3) : "r"(addr));
}

__device__ __forceinline__ void mma16816(float* c, const uint32_t* a, const uint32_t* b) {
    asm volatile(
        "mma.sync.aligned.m16n8k16.row.col.f32.f16.f16.f32 "
        "{%0,%1,%2,%3}, {%4,%5,%6,%7}, {%8,%9}, {%0,%1,%2,%3};"
        : "+f"(c[0]), "+f"(c[1]), "+f"(c[2]), "+f"(c[3])
        : "r"(a[0]), "r"(a[1]), "r"(a[2]), "r"(a[3]), "r"(b[0]), "r"(b[1]));
}

__device__ __forceinline__ uint32_t pack_half2(float a, float b) {
    __half2 h = __floats2half2_rn(a, b);
    return *(uint32_t*)&h;
}

__device__ __forceinline__ void cp_async16(uint32_t dst, const void* src) {
    asm volatile("cp.async.cg.shared.global [%0], [%1], 16;" :: "r"(dst), "l"(src));
}
#define CP_COMMIT() asm volatile("cp.async.commit_group;")
#define CP_WAIT0()  asm volatile("cp.async.wait_group 0;" ::: "memory")

// ============================================================================
// Prep 1: transpose x [B,C,E] -> g_xt [B,E,C]. 128e x 32c tiles, float4 I/O.
// ============================================================================
__global__ void transpose_kernel(const float* __restrict__ x) {
    __shared__ float tile[32 * 132];
    const int b  = blockIdx.z;
    const int c0 = blockIdx.y * 32;
    const int e0 = blockIdx.x * 128;
    const int tid = threadIdx.x;              // 256

    #pragma unroll
    for (int i = 0; i < 4; ++i) {
        const int idx = tid + i * 256;
        const int c = idx >> 5;
        const int q = idx & 31;
        const int e = e0 + q * 4;
        float4 v = make_float4(0.f, 0.f, 0.f, 0.f);
        if (e < E)   // E % 4 == 0
            v = *(const float4*)(x + ((size_t)b * CIN + c0 + c) * E + e);
        *(float4*)(tile + c * 132 + q * 4) = v;
    }
    __syncthreads();

    #pragma unroll
    for (int i = 0; i < 4; ++i) {
        const int idx = tid + i * 256;
        const int e = idx >> 3;
        const int m = idx & 7;
        const int c = m * 4;
        if (e0 + e < E) {
            float4 v;
            v.x = tile[(c + 0) * 132 + e];
            v.y = tile[(c + 1) * 132 + e];
            v.z = tile[(c + 2) * 132 + e];
            v.w = tile[(c + 3) * 132 + e];
            *(float4*)(g_xt + ((size_t)b * E + e0 + e) * CIN + c0 + c) = v;
        }
    }
}

// ============================================================================
// Prep 2: convert conv_w to fp16, k-major MMA layout
// ============================================================================
__global__ void wprep_kernel(const float* __restrict__ w) {
    int idx = blockIdx.x * 256 + threadIdx.x;
    if (idx >= COUT * CIN * TAPS) return;
    int tap = idx % TAPS;
    int c   = (idx / TAPS) % CIN;
    int n   = idx / (TAPS * CIN);
    int chalf = c >> 6, j = c & 63;
    g_w[((tap * 2 + chalf) * COUT + n) * 64 + j] = __float2half_rn(w[idx]);
}

// ============================================================================
// Main kernel
// ============================================================================
static constexpr int SMEM_BIAS = 0;                 // 1 KB
static constexpr int SMEM_A    = 1024;              // 3 slots x 16KB = 48KB
static constexpr int SMEM_B    = 1024 + 3 * 16384;  // 2 bufs x 32KB = 64KB
static constexpr int SMEM_TOTAL = SMEM_B + 2 * 32768;   // 115712 B

#define A_H(slot) (SMEM_A + (slot) * 16384)
#define B_H(buf)  (SMEM_B + (buf) * 32768)

__global__ void __launch_bounds__(512, 1) mesh_main(
    const int* __restrict__ ne_idx,
    const float* __restrict__ bias,
    float* __restrict__ out)
{
    extern __shared__ char smem[];
    const uint32_t smem_base = smem_u32(smem);
    const int tid  = threadIdx.x;
    const int wid  = tid >> 5;
    const int lane = tid & 31;

    const int blk    = blockIdx.x;
    const int b      = blk / ETILES;
    const int et     = blk % ETILES;
    const int ebase  = et * ETILE;
    const int evalid = min(ETILE, E - ebase);

    if (tid < 256) ((float*)(smem + SMEM_BIAS))[tid] = bias[tid];

    const int warp_m = wid & 3;
    const int warp_n = wid >> 2;
    const int m0w = warp_m * 32;
    const int n0w = warp_n * 64;

    float acc[2][8][4];
    #pragma unroll
    for (int i = 0; i < 2; ++i)
        #pragma unroll
        for (int j = 0; j < 8; ++j)
            #pragma unroll
            for (int q = 0; q < 4; ++q) acc[i][j][q] = 0.f;

    const float* xtb = g_xt + (size_t)b * E * CIN;
    const int*   nb  = ne_idx + ((size_t)b * E + ebase) * 4;

    // ldmatrix lane addressing
    const int a_row = lane & 15;
    const int a_kof = (lane >> 4) << 3;
    const int b_row = (lane & 7) + ((lane & 16) ? 8 : 0);
    const int b_kof = (lane & 8) ? 8 : 0;

    // gather fill mapping: 16 threads/edge, 4 channels/thread
    const int gj0 = (tid & 15) * 4;
    const int gm0 = tid >> 4;

    // ---------------- Prologue: stage 0 = (tap0, chalf0) ----------------
    {
        #pragma unroll
        for (int q = 0; q < 4; ++q) {
            int i = tid + q * 512;
            uint32_t off = SMEM_SWIZZLE_128B((uint32_t)((i >> 3) * 128 + (i & 7) * 16));
            cp_async16(smem_base + B_H(0) + off, (const char*)g_w + i * 16);
        }
        CP_COMMIT();
        #pragma unroll
        for (int pass = 0; pass < 4; ++pass) {
            const int m = pass * 32 + gm0;
            float4 a = make_float4(0.f, 0.f, 0.f, 0.f);
            if (m < evalid)
                a = *(const float4*)(xtb + (size_t)(ebase + m) * CIN + gj0);
            uint32_t off = SMEM_SWIZZLE_128B((uint32_t)(m * 128 + gj0 * 2));
            *(uint2*)(smem + A_H(0) + off) =
                make_uint2(pack_half2(a.x, a.y), pack_half2(a.z, a.w));
        }
        CP_WAIT0();
        __syncthreads();
    }

    // ---------------- Main pipeline ----------------
    for (int s = 0; s < NSTAGES; ++s) {
        const int as  = s % 3;
        const int buf = s & 1;
        const int nxt = s + 1;

        int fkind = 0;            // 0 none, 1 self, 2 pair(sum+abs)
        int n_tap = 0, n_c0 = 0, slotS = 0, slotA = 0;
        if (nxt < NSTAGES) {
            const int npos = (nxt < 5) ? nxt : nxt - 5;
            n_tap = STAGE_TAP(npos);
            n_c0  = (nxt >= 5) ? 64 : 0;
            slotS = nxt % 3;
            slotA = (s + 2) % 3;
            if (n_tap == 0) fkind = 1;
            else if (n_tap == 1 || n_tap == 2) fkind = 2;

            // B fill for next stage via cp.async
            const int widx = n_tap * 2 + ((nxt >= 5) ? 1 : 0);
            const __half* srcH = g_w + (size_t)widx * COUT * 64;
            const uint32_t dH = smem_base + B_H(buf ^ 1);
            #pragma unroll
            for (int q = 0; q < 4; ++q) {
                int i = tid + q * 512;
                uint32_t off = SMEM_SWIZZLE_128B((uint32_t)((i >> 3) * 128 + (i & 7) * 16));
                cp_async16(dH + off, (const char*)srcH + i * 16);
            }
            CP_COMMIT();
        }

        const uint32_t aBH = smem_base + A_H(as);
        const uint32_t bBH = smem_base + B_H(buf);

        // gather prefetch for pass 0
        float4 ga = make_float4(0.f, 0.f, 0.f, 0.f);
        float4 gc = make_float4(0.f, 0.f, 0.f, 0.f);
        if (fkind == 1) {
            if (gm0 < evalid)
                ga = *(const float4*)(xtb + (size_t)(ebase + gm0) * CIN + n_c0 + gj0);
        } else if (fkind == 2) {
            if (gm0 < evalid) {
                const int4 nbr = *(const int4*)(nb + gm0 * 4);
                const int ia = (n_tap == 1) ? nbr.x : nbr.y;
                const int ib = (n_tap == 1) ? nbr.z : nbr.w;
                ga = *(const float4*)(xtb + (size_t)ia * CIN + n_c0 + gj0);
                gc = *(const float4*)(xtb + (size_t)ib * CIN + n_c0 + gj0);
            }
        }

        #pragma unroll
        for (int kk = 0; kk < 4; ++kk) {
            // issue gather for pass kk+1 (latency hidden under MMAs below)
            float4 gan = make_float4(0.f, 0.f, 0.f, 0.f);
            float4 gcn = make_float4(0.f, 0.f, 0.f, 0.f);
            if (kk < 3) {
                const int gm = (kk + 1) * 32 + gm0;
                if (fkind == 1) {
                    if (gm < evalid)
                        gan = *(const float4*)(xtb + (size_t)(ebase + gm) * CIN + n_c0 + gj0);
                } else if (fkind == 2) {
                    if (gm < evalid) {
                        const int4 nbr = *(const int4*)(nb + gm * 4);
                        const int ia = (n_tap == 1) ? nbr.x : nbr.y;
                        const int ib = (n_tap == 1) ? nbr.z : nbr.w;
                        gan = *(const float4*)(xtb + (size_t)ia * CIN + n_c0 + gj0);
                        gcn = *(const float4*)(xtb + (size_t)ib * CIN + n_c0 + gj0);
                    }
                }
            }

            // ---- compute chunk kk: 16 HMMA ----
            {
                const int kcol = kk * 16 + a_kof;
                uint32_t ah[2][4], bf[8][2];
                #pragma unroll
                for (int mt = 0; mt < 2; ++mt) {
                    const int row = m0w + mt * 16 + a_row;
                    uint32_t off = SMEM_SWIZZLE_128B((uint32_t)(row * 128 + kcol * 2));
                    ldsm_x4(ah[mt][0], ah[mt][1], ah[mt][2], ah[mt][3], aBH + off);
                }
                #pragma unroll
                for (int nbq = 0; nbq < 4; ++nbq) {
                    const int row = n0w + nbq * 16 + b_row;
                    uint32_t off = SMEM_SWIZZLE_128B((uint32_t)(row * 128 + (kk * 16 + b_kof) * 2));
                    ldsm_x4(bf[nbq * 2][0], bf[nbq * 2][1],
                            bf[nbq * 2 + 1][0], bf[nbq * 2 + 1][1], bBH + off);
                }
                #pragma unroll
                for (int mt = 0; mt < 2; ++mt)
                    #pragma unroll
                    for (int j = 0; j < 8; ++j) mma16816(acc[mt][j], ah[mt], bf[j]);
            }

            // ---- convert + STS for pass kk ----
            {
                const int gm = kk * 32 + gm0;
                uint32_t off = SMEM_SWIZZLE_128B((uint32_t)(gm * 128 + gj0 * 2));
                if (fkind == 1) {
                    *(uint2*)(smem + A_H(slotS) + off) =
                        make_uint2(pack_half2(ga.x, ga.y), pack_half2(ga.z, ga.w));
                } else if (fkind == 2) {
                    *(uint2*)(smem + A_H(slotS) + off) =
                        make_uint2(pack_half2(ga.x + gc.x, ga.y + gc.y),
                                   pack_half2(ga.z + gc.z, ga.w + gc.w));
                    *(uint2*)(smem + A_H(slotA) + off) =
                        make_uint2(pack_half2(fabsf(ga.x - gc.x), fabsf(ga.y - gc.y)),
                                   pack_half2(fabsf(ga.z - gc.z), fabsf(ga.w - gc.w)));
                }
            }
            ga = gan; gc = gcn;
        }

        if (nxt < NSTAGES) CP_WAIT0();
        __syncthreads();
    }

    // ---------------- Epilogue: +bias, store out[b][o][e] ----------------
    {
        const float* bsm = (const float*)(smem + SMEM_BIAS);
        float* obase = out + (size_t)b * COUT * E;
        #pragma unroll
        for (int mt = 0; mt < 2; ++mt) {
            const int r0 = m0w + mt * 16 + (lane >> 2);
            const int r1 = r0 + 8;
            const bool ok0 = r0 < evalid;
            const bool ok1 = r1 < evalid;
            #pragma unroll
            for (int j = 0; j < 8; ++j) {
                const int o = n0w + j * 8 + 2 * (lane & 3);
                const float b0 = bsm[o], b1 = bsm[o + 1];
                float* p0 = obase + (size_t)o * E;
                float* p1 = obase + (size_t)(o + 1) * E;
                if (ok0) {
                    p0[ebase + r0] = acc[mt][j][0] + b0;
                    p1[ebase + r0] = acc[mt][j][1] + b1;
                }
                if (ok1) {
                    p0[ebase + r1] = acc[mt][j][2] + b0;
                    p1[ebase + r1] = acc[mt][j][3] + b1;
                }
            }
        }
    }
}

// ============================================================================
// Launch
// ============================================================================
extern "C" void kernel_launch(void* const* d_in, const int* in_sizes, int n_in,
                              void* d_out, int out_size) {
    const float* x    = (const float*)d_in[0];
    const int*   ne   = (const int*)d_in[1];
    const float* w    = (const float*)d_in[2];
    const float* bias = (const float*)d_in[3];
    float*       out  = (float*)d_out;

    cudaFuncSetAttribute(mesh_main, cudaFuncAttributeMaxDynamicSharedMemorySize, SMEM_TOTAL);

    dim3 tgrid((E + 127) / 128, CIN / 32, BATCH);
    transpose_kernel<<<tgrid, 256>>>(x);
    wprep_kernel<<<(COUT * CIN * TAPS + 255) / 256, 256>>>(w);
    mesh_main<<<NBLOCKS, 512, SMEM_TOTAL>>>(ne, bias, out);
}

// round 8
// speedup vs baseline: 2.7537x; 1.2024x over previous
#include <cuda_runtime.h>
#include <cuda_fp16.h>
#include <cstdint>

// ============================================================================
// out[b,o,e] = sum_{c,k} G[b,c,e,k] * W[o,c,k] + bias[o]
//   G taps: [self, n0+n2, n1+n3, |n0-n2|, |n1-n3|]
// GEMM [COUT=256] x [K'=640] x [B*E=120000], fp16 operands / fp32 accum.
// g_xt stored fp16; 5 merged stages of K=128 (tap order 0,1,3,2,4).
// Pair stages (s=0 fills taps1&3, s=2 fills taps2&4) share neighbor gathers.
// ldmatrix + mma.sync.m16n8k16 (tcgen05 rejected by ptxas on compute_103).
// ============================================================================
static constexpr int BATCH = 4;
static constexpr int CIN   = 128;
static constexpr int COUT  = 256;
static constexpr int E     = 30000;
static constexpr int TAPS  = 5;

static constexpr int ETILE   = 128;
static constexpr int ETILES  = (E + ETILE - 1) / ETILE;   // 235
static constexpr int NBLOCKS = BATCH * ETILES;            // 940

// tap order: 0,1,3,2,4
#define STAGE_TAP(pos) ((int)((0x42310u >> ((pos) * 4)) & 0xF))

// ============================================================================
// Device scratch
// ============================================================================
__device__ __half g_xt16[(size_t)BATCH * E * CIN];   // x transposed [B,E,C] fp16
__device__ __half g_w[TAPS * 2 * COUT * 64];         // [tap][khalf][n][64]

// ============================================================================
// Helpers
// ============================================================================
__device__ __forceinline__ uint32_t smem_u32(const void* p) {
    uint32_t a;
    asm("{ .reg .u64 t; cvta.to.shared.u64 t, %1; cvt.u32.u64 %0, t; }"
        : "=r"(a) : "l"(p));
    return a;
}

#define SMEM_SWIZZLE_128B(off) ((off) ^ (((off) >> 3) & 0x70))

__device__ __forceinline__ void ldsm_x4(uint32_t& r0, uint32_t& r1,
                                        uint32_t& r2, uint32_t& r3, uint32_t addr) {
    asm volatile("ldmatrix.sync.aligned.m8n8.x4.shared.b16 {%0,%1,%2,%3}, [%4];"
                 : "=r"(r0), "=r"(r1), "=r"(r2), "=r"(r3) : "r"(addr));
}

__device__ __forceinline__ void mma16816(float* c, const uint32_t* a, const uint32_t* b) {
    asm volatile(
        "mma.sync.aligned.m16n8k16.row.col.f32.f16.f16.f32 "
        "{%0,%1,%2,%3}, {%4,%5,%6,%7}, {%8,%9}, {%0,%1,%2,%3};"
        : "+f"(c[0]), "+f"(c[1]), "+f"(c[2]), "+f"(c[3])
        : "r"(a[0]), "r"(a[1]), "r"(a[2]), "r"(a[3]), "r"(b[0]), "r"(b[1]));
}

__device__ __forceinline__ uint32_t pack_half2(float a, float b) {
    __half2 h = __floats2half2_rn(a, b);
    return *(uint32_t*)&h;
}

__device__ __forceinline__ void cp_async16(uint32_t dst, const void* src) {
    asm volatile("cp.async.cg.shared.global [%0], [%1], 16;" :: "r"(dst), "l"(src));
}
__device__ __forceinline__ void cp_async16_zfill(uint32_t dst, const void* src) {
    asm volatile("cp.async.cg.shared.global [%0], [%1], 16, 0;" :: "r"(dst), "l"(src));
}
#define CP_COMMIT() asm volatile("cp.async.commit_group;")
#define CP_WAIT0()  asm volatile("cp.async.wait_group 0;" ::: "memory")

// half2 vector combine on uint4 (8 halves)
__device__ __forceinline__ uint4 h2_add4(uint4 a, uint4 b) {
    uint4 r;
    #pragma unroll
    for (int i = 0; i < 4; ++i)
        ((__half2*)&r)[i] = __hadd2(((const __half2*)&a)[i], ((const __half2*)&b)[i]);
    return r;
}
__device__ __forceinline__ uint4 h2_absdiff4(uint4 a, uint4 b) {
    uint4 r;
    #pragma unroll
    for (int i = 0; i < 4; ++i)
        ((__half2*)&r)[i] = __habs2(__hsub2(((const __half2*)&a)[i], ((const __half2*)&b)[i]));
    return r;
}

// ============================================================================
// Prep 1: transpose x [B,C,E] f32 -> g_xt16 [B,E,C] fp16. 128e x 32c tiles.
// NOTE: tile row stride must keep float4 stores 16B-aligned -> 132 floats.
// ============================================================================
__global__ void transpose_kernel(const float* __restrict__ x) {
    __shared__ float tile[32 * 132];
    const int b  = blockIdx.z;
    const int c0 = blockIdx.y * 32;
    const int e0 = blockIdx.x * 128;
    const int tid = threadIdx.x;              // 256

    #pragma unroll
    for (int i = 0; i < 4; ++i) {
        const int idx = tid + i * 256;
        const int c = idx >> 5;
        const int q = idx & 31;
        const int e = e0 + q * 4;
        float4 v = make_float4(0.f, 0.f, 0.f, 0.f);
        if (e < E)   // E % 4 == 0
            v = *(const float4*)(x + ((size_t)b * CIN + c0 + c) * E + e);
        *(float4*)(tile + c * 132 + q * 4) = v;
    }
    __syncthreads();

    #pragma unroll
    for (int i = 0; i < 2; ++i) {
        const int idx = tid + i * 256;        // 512: e = idx>>2, 8ch group = idx&3
        const int e = idx >> 2;
        const int g = (idx & 3) * 8;
        if (e0 + e < E) {
            uint4 v;
            uint32_t* pv = (uint32_t*)&v;
            #pragma unroll
            for (int h = 0; h < 4; ++h) {
                pv[h] = pack_half2(tile[(g + 2 * h) * 132 + e],
                                   tile[(g + 2 * h + 1) * 132 + e]);
            }
            *(uint4*)(g_xt16 + ((size_t)b * E + e0 + e) * CIN + c0 + g) = v;
        }
    }
}

// ============================================================================
// Prep 2: convert conv_w to fp16, [tap][khalf][n][64] k-major layout
// ============================================================================
__global__ void wprep_kernel(const float* __restrict__ w) {
    int idx = blockIdx.x * 256 + threadIdx.x;
    if (idx >= COUT * CIN * TAPS) return;
    int tap = idx % TAPS;
    int c   = (idx / TAPS) % CIN;
    int n   = idx / (TAPS * CIN);
    int kh = c >> 6, j = c & 63;
    g_w[((tap * 2 + kh) * COUT + n) * 64 + j] = __float2half_rn(w[idx]);
}

// ============================================================================
// Main kernel: 512 threads, 16 warps (4m x 4n), warp tile 32m x 64n.
// A tile 128m x 128k fp16 = 2 x 16KB khalf sub-tiles (SW128 each).
// B tile 256n x 128k fp16 = 2 x 32KB khalf sub-tiles.
// ============================================================================
static constexpr int SMEM_BIAS = 0;                 // 1 KB
static constexpr int SMEM_A    = 1024;              // 3 slots x 32KB
static constexpr int SMEM_B    = 1024 + 3 * 32768;  // 2 bufs x 64KB
static constexpr int SMEM_TOTAL = SMEM_B + 2 * 65536;   // 230400 B

#define A_H(slot) (SMEM_A + (slot) * 32768)
#define B_H(buf)  (SMEM_B + (buf) * 65536)

__global__ void __launch_bounds__(512, 1) mesh_main(
    const int* __restrict__ ne_idx,
    const float* __restrict__ bias,
    float* __restrict__ out)
{
    extern __shared__ char smem[];
    const uint32_t smem_base = smem_u32(smem);
    const int tid  = threadIdx.x;
    const int wid  = tid >> 5;
    const int lane = tid & 31;

    const int blk    = blockIdx.x;
    const int b      = blk / ETILES;
    const int et     = blk % ETILES;
    const int ebase  = et * ETILE;
    const int evalid = min(ETILE, E - ebase);

    if (tid < 256) ((float*)(smem + SMEM_BIAS))[tid] = bias[tid];

    const int warp_m = wid & 3;
    const int warp_n = wid >> 2;
    const int m0w = warp_m * 32;
    const int n0w = warp_n * 64;

    float acc[2][8][4];
    #pragma unroll
    for (int i = 0; i < 2; ++i)
        #pragma unroll
        for (int j = 0; j < 8; ++j)
            #pragma unroll
            for (int q = 0; q < 4; ++q) acc[i][j][q] = 0.f;

    const __half* xtb = g_xt16 + (size_t)b * E * CIN;
    const int*    nb  = ne_idx + ((size_t)b * E + ebase) * 4;

    // ldmatrix lane addressing
    const int a_row = lane & 15;
    const int a_kof = (lane >> 4) << 3;
    const int b_row = (lane & 7) + ((lane & 16) ? 8 : 0);
    const int b_kof = (lane & 8) ? 8 : 0;

    // gather fill mapping: 16 threads/edge, 8 fp16 channels/thread
    const int gj0 = (tid & 15) * 8;
    const int gm0 = tid >> 4;                  // edge within 32-edge pass
    const uint32_t g_koff = (uint32_t)(gj0 >> 6) * 16384;   // khalf sub-tile

    // ---------------- Prologue: B(tap0) + A slot0 (self rows, contiguous) ----
    {
        #pragma unroll
        for (int q = 0; q < 8; ++q) {          // B: 4096 x 16B
            int i = tid + q * 512;
            uint32_t off = (uint32_t)(i >> 11) * 32768 +
                SMEM_SWIZZLE_128B((uint32_t)(((i & 2047) >> 3) * 128 + (i & 7) * 16));
            cp_async16(smem_base + B_H(0) + off, (const char*)g_w + i * 16);
        }
        #pragma unroll
        for (int q = 0; q < 4; ++q) {          // A: 2048 x 16B
            int i = tid + q * 512;
            const int m = i >> 4;
            const int part = i & 15;
            uint32_t off = (uint32_t)(part >> 3) * 16384 +
                SMEM_SWIZZLE_128B((uint32_t)(m * 128 + (part & 7) * 16));
            const __half* src = xtb + (size_t)(ebase + m) * CIN + part * 8;
            if (m < evalid) cp_async16(smem_base + A_H(0) + off, src);
            else            cp_async16_zfill(smem_base + A_H(0) + off, xtb);
        }
        CP_COMMIT();
        CP_WAIT0();
        __syncthreads();
    }

    // ---------------- 5 merged stages ----------------
    for (int s = 0; s < 5; ++s) {
        const int slot = s % 3;
        const int buf  = s & 1;
        const bool do_fill = (s == 0) || (s == 2);
        const int slotS = (s + 1) % 3;
        const int slotA = (s + 2) % 3;
        const bool useXZ = (s == 0);

        // B fill for next stage
        if (s < 4) {
            const __half* srcB = g_w + (size_t)STAGE_TAP(s + 1) * (2 * COUT * 64);
            const uint32_t dB = smem_base + B_H(buf ^ 1);
            #pragma unroll
            for (int q = 0; q < 8; ++q) {
                int i = tid + q * 512;
                uint32_t off = (uint32_t)(i >> 11) * 32768 +
                    SMEM_SWIZZLE_128B((uint32_t)(((i & 2047) >> 3) * 128 + (i & 7) * 16));
                cp_async16(dB + off, (const char*)srcB + i * 16);
            }
            CP_COMMIT();
        }

        const uint32_t aB = smem_base + A_H(slot);
        const uint32_t bB = smem_base + B_H(buf);

        // gather prefetch for pass 0
        uint4 ga = make_uint4(0, 0, 0, 0);
        uint4 gc = make_uint4(0, 0, 0, 0);
        if (do_fill && gm0 < evalid) {
            const int4 nbr = *(const int4*)(nb + gm0 * 4);
            const int ia = useXZ ? nbr.x : nbr.y;
            const int ib = useXZ ? nbr.z : nbr.w;
            ga = *(const uint4*)(xtb + (size_t)ia * CIN + gj0);
            gc = *(const uint4*)(xtb + (size_t)ib * CIN + gj0);
        }

        #pragma unroll
        for (int kk = 0; kk < 8; ++kk) {
            // prefetch gathers for pass kk+1
            uint4 gan = make_uint4(0, 0, 0, 0);
            uint4 gcn = make_uint4(0, 0, 0, 0);
            if (do_fill && kk < 3) {
                const int gm = (kk + 1) * 32 + gm0;
                if (gm < evalid) {
                    const int4 nbr = *(const int4*)(nb + gm * 4);
                    const int ia = useXZ ? nbr.x : nbr.y;
                    const int ib = useXZ ? nbr.z : nbr.w;
                    gan = *(const uint4*)(xtb + (size_t)ia * CIN + gj0);
                    gcn = *(const uint4*)(xtb + (size_t)ib * CIN + gj0);
                }
            }

            // ---- compute chunk kk: 16 HMMA ----
            {
                const uint32_t akh = (uint32_t)(kk >> 2) * 16384;
                const uint32_t bkh = (uint32_t)(kk >> 2) * 32768;
                const int kc = (kk & 3) * 16;
                uint32_t ah[2][4], bf[8][2];
                #pragma unroll
                for (int mt = 0; mt < 2; ++mt) {
                    const int row = m0w + mt * 16 + a_row;
                    uint32_t off = SMEM_SWIZZLE_128B((uint32_t)(row * 128 + (kc + a_kof) * 2));
                    ldsm_x4(ah[mt][0], ah[mt][1], ah[mt][2], ah[mt][3], aB + akh + off);
                }
                #pragma unroll
                for (int nbq = 0; nbq < 4; ++nbq) {
                    const int row = n0w + nbq * 16 + b_row;
                    uint32_t off = SMEM_SWIZZLE_128B((uint32_t)(row * 128 + (kc + b_kof) * 2));
                    ldsm_x4(bf[nbq * 2][0], bf[nbq * 2][1],
                            bf[nbq * 2 + 1][0], bf[nbq * 2 + 1][1], bB + bkh + off);
                }
                #pragma unroll
                for (int mt = 0; mt < 2; ++mt)
                    #pragma unroll
                    for (int j = 0; j < 8; ++j) mma16816(acc[mt][j], ah[mt], bf[j]);
            }

            // ---- combine + STS for pass kk (sum -> slotS, abs -> slotA) ----
            if (do_fill && kk < 4) {
                const int gm = kk * 32 + gm0;
                const uint32_t off = g_koff +
                    SMEM_SWIZZLE_128B((uint32_t)(gm * 128 + (gj0 & 63) * 2));
                *(uint4*)(smem + A_H(slotS) + off) = h2_add4(ga, gc);
                *(uint4*)(smem + A_H(slotA) + off) = h2_absdiff4(ga, gc);
                ga = gan; gc = gcn;
            }
        }

        if (s < 4) CP_WAIT0();
        __syncthreads();
    }

    // ---------------- Epilogue: +bias, store out[b][o][e] ----------------
    {
        const float* bsm = (const float*)(smem + SMEM_BIAS);
        float* obase = out + (size_t)b * COUT * E;
        #pragma unroll
        for (int mt = 0; mt < 2; ++mt) {
            const int r0 = m0w + mt * 16 + (lane >> 2);
            const int r1 = r0 + 8;
            const bool ok0 = r0 < evalid;
            const bool ok1 = r1 < evalid;
            #pragma unroll
            for (int j = 0; j < 8; ++j) {
                const int o = n0w + j * 8 + 2 * (lane & 3);
                const float b0 = bsm[o], b1 = bsm[o + 1];
                float* p0 = obase + (size_t)o * E;
                float* p1 = obase + (size_t)(o + 1) * E;
                if (ok0) {
                    p0[ebase + r0] = acc[mt][j][0] + b0;
                    p1[ebase + r0] = acc[mt][j][1] + b1;
                }
                if (ok1) {
                    p0[ebase + r1] = acc[mt][j][2] + b0;
                    p1[ebase + r1] = acc[mt][j][3] + b1;
                }
            }
        }
    }
}

// ============================================================================
// Launch
// ============================================================================
extern "C" void kernel_launch(void* const* d_in, const int* in_sizes, int n_in,
                              void* d_out, int out_size) {
    const float* x    = (const float*)d_in[0];
    const int*   ne   = (const int*)d_in[1];
    const float* w    = (const float*)d_in[2];
    const float* bias = (const float*)d_in[3];
    float*       out  = (float*)d_out;

    cudaFuncSetAttribute(mesh_main, cudaFuncAttributeMaxDynamicSharedMemorySize, SMEM_TOTAL);

    dim3 tgrid((E + 127) / 128, CIN / 32, BATCH);
    transpose_kernel<<<tgrid, 256>>>(x);
    wprep_kernel<<<(COUT * CIN * TAPS + 255) / 256, 256>>>(w);
    mesh_main<<<NBLOCKS, 512, SMEM_TOTAL>>>(ne, bias, out);
}

// round 9
// speedup vs baseline: 3.1297x; 1.1365x over previous
#include <cuda_runtime.h>
#include <cuda_fp16.h>
#include <cstdint>

// ============================================================================
// out[b,o,e] = sum_{c,k} G[b,c,e,k] * W[o,c,k] + bias[o]
//   G taps: [self, n0+n2, n1+n3, |n0-n2|, |n1-n3|]
// GEMM [COUT=256] x [K'=640] x [B*E=120000], fp16 operands / fp32 accum.
// g_xt stored fp16; 5 merged stages of K=128 (tap order 0,1,3,2,4).
// Pair stages (s=0 fills taps1&3, s=2 fills taps2&4) share neighbor gathers.
// ldmatrix + mma.sync.m16n8k16 (tcgen05 rejected by ptxas on compute_103).
// Main kernel measured at ~90-98% of the classic HMMA issue ceiling.
// ============================================================================
static constexpr int BATCH = 4;
static constexpr int CIN   = 128;
static constexpr int COUT  = 256;
static constexpr int E     = 30000;
static constexpr int TAPS  = 5;

static constexpr int ETILE   = 128;
static constexpr int ETILES  = (E + ETILE - 1) / ETILE;   // 235
static constexpr int NBLOCKS = BATCH * ETILES;            // 940

// tap order: 0,1,3,2,4
#define STAGE_TAP(pos) ((int)((0x42310u >> ((pos) * 4)) & 0xF))

// ============================================================================
// Device scratch
// ============================================================================
__device__ __half g_xt16[(size_t)BATCH * E * CIN];   // x transposed [B,E,C] fp16
__device__ __half g_w[TAPS * 2 * COUT * 64];         // [tap][khalf][n][64]

// ============================================================================
// Helpers
// ============================================================================
__device__ __forceinline__ uint32_t smem_u32(const void* p) {
    uint32_t a;
    asm("{ .reg .u64 t; cvta.to.shared.u64 t, %1; cvt.u32.u64 %0, t; }"
        : "=r"(a) : "l"(p));
    return a;
}

#define SMEM_SWIZZLE_128B(off) ((off) ^ (((off) >> 3) & 0x70))

__device__ __forceinline__ void ldsm_x4(uint32_t& r0, uint32_t& r1,
                                        uint32_t& r2, uint32_t& r3, uint32_t addr) {
    asm volatile("ldmatrix.sync.aligned.m8n8.x4.shared.b16 {%0,%1,%2,%3}, [%4];"
                 : "=r"(r0), "=r"(r1), "=r"(r2), "=r"(r3) : "r"(addr));
}

__device__ __forceinline__ void mma16816(float* c, const uint32_t* a, const uint32_t* b) {
    asm volatile(
        "mma.sync.aligned.m16n8k16.row.col.f32.f16.f16.f32 "
        "{%0,%1,%2,%3}, {%4,%5,%6,%7}, {%8,%9}, {%0,%1,%2,%3};"
        : "+f"(c[0]), "+f"(c[1]), "+f"(c[2]), "+f"(c[3])
        : "r"(a[0]), "r"(a[1]), "r"(a[2]), "r"(a[3]), "r"(b[0]), "r"(b[1]));
}

__device__ __forceinline__ uint32_t pack_half2(float a, float b) {
    __half2 h = __floats2half2_rn(a, b);
    return *(uint32_t*)&h;
}

__device__ __forceinline__ void cp_async16(uint32_t dst, const void* src) {
    asm volatile("cp.async.cg.shared.global [%0], [%1], 16;" :: "r"(dst), "l"(src));
}
__device__ __forceinline__ void cp_async16_zfill(uint32_t dst, const void* src) {
    asm volatile("cp.async.cg.shared.global [%0], [%1], 16, 0;" :: "r"(dst), "l"(src));
}
#define CP_COMMIT() asm volatile("cp.async.commit_group;")
#define CP_WAIT0()  asm volatile("cp.async.wait_group 0;" ::: "memory")

// half2 vector combine on uint4 (8 halves)
__device__ __forceinline__ uint4 h2_add4(uint4 a, uint4 b) {
    uint4 r;
    #pragma unroll
    for (int i = 0; i < 4; ++i)
        ((__half2*)&r)[i] = __hadd2(((const __half2*)&a)[i], ((const __half2*)&b)[i]);
    return r;
}
__device__ __forceinline__ uint4 h2_absdiff4(uint4 a, uint4 b) {
    uint4 r;
    #pragma unroll
    for (int i = 0; i < 4; ++i)
        ((__half2*)&r)[i] = __habs2(__hsub2(((const __half2*)&a)[i], ((const __half2*)&b)[i]));
    return r;
}

// ============================================================================
// Prep 1: transpose x [B,C,E] f32 -> g_xt16 [B,E,C] fp16. 128e x 32c tiles.
// Tile stored as uint4[32][32] with XOR swizzle j ^= (c>>3)&3 so that the
// phase-2 column reads (c spaced by 8) hit distinct banks.
// ============================================================================
__global__ void transpose_kernel(const float* __restrict__ x) {
    __shared__ uint4 tile4[32 * 32];          // 16 KB, [c][j] swizzled
    const int b  = blockIdx.z;
    const int c0 = blockIdx.y * 32;
    const int e0 = blockIdx.x * 128;
    const int tid = threadIdx.x;              // 256

    // Phase 1: 32 c-rows x 32 float4 along e (coalesced LDG.128 + STS.128)
    #pragma unroll
    for (int i = 0; i < 4; ++i) {
        const int idx = tid + i * 256;
        const int c = idx >> 5;
        const int j = idx & 31;
        const int e = e0 + j * 4;
        float4 v = make_float4(0.f, 0.f, 0.f, 0.f);
        if (e < E)   // E % 4 == 0
            v = *(const float4*)(x + ((size_t)b * CIN + c0 + c) * E + e);
        tile4[c * 32 + (j ^ ((c >> 3) & 3))] = *(const uint4*)&v;
    }
    __syncthreads();

    // Phase 2: per thread one (e, 8-channel group) -> pack fp16 + STG.128
    const float* tf = (const float*)tile4;
    #pragma unroll
    for (int i = 0; i < 2; ++i) {
        const int idx = tid + i * 256;        // 512 items: e = idx>>2, grp = idx&3
        const int e = idx >> 2;
        const int g = (idx & 3) * 8;
        if (e0 + e < E) {
            uint4 v;
            uint32_t* pv = (uint32_t*)&v;
            const int j  = e >> 2;
            const int el = e & 3;
            #pragma unroll
            for (int h = 0; h < 4; ++h) {
                const int ca = g + 2 * h;
                const int jx = (j ^ ((ca >> 3) & 3)) * 4 + el;
                pv[h] = pack_half2(tf[ca * 128 + jx], tf[(ca + 1) * 128 + jx]);
            }
            *(uint4*)(g_xt16 + ((size_t)b * E + e0 + e) * CIN + c0 + g) = v;
        }
    }
}

// ============================================================================
// Prep 2: convert conv_w to fp16, [tap][khalf][n][64] k-major layout
// ============================================================================
__global__ void wprep_kernel(const float* __restrict__ w) {
    int idx = blockIdx.x * 256 + threadIdx.x;
    if (idx >= COUT * CIN * TAPS) return;
    int tap = idx % TAPS;
    int c   = (idx / TAPS) % CIN;
    int n   = idx / (TAPS * CIN);
    int kh = c >> 6, j = c & 63;
    g_w[((tap * 2 + kh) * COUT + n) * 64 + j] = __float2half_rn(w[idx]);
}

// ============================================================================
// Main kernel: 512 threads, 16 warps (4m x 4n), warp tile 32m x 64n.
// A tile 128m x 128k fp16 = 2 x 16KB khalf sub-tiles (SW128 each).
// B tile 256n x 128k fp16 = 2 x 32KB khalf sub-tiles.
// ============================================================================
static constexpr int SMEM_BIAS = 0;                 // 1 KB
static constexpr int SMEM_A    = 1024;              // 3 slots x 32KB
static constexpr int SMEM_B    = 1024 + 3 * 32768;  // 2 bufs x 64KB
static constexpr int SMEM_TOTAL = SMEM_B + 2 * 65536;   // 230400 B

#define A_H(slot) (SMEM_A + (slot) * 32768)
#define B_H(buf)  (SMEM_B + (buf) * 65536)

__global__ void __launch_bounds__(512, 1) mesh_main(
    const int* __restrict__ ne_idx,
    const float* __restrict__ bias,
    float* __restrict__ out)
{
    extern __shared__ char smem[];
    const uint32_t smem_base = smem_u32(smem);
    const int tid  = threadIdx.x;
    const int wid  = tid >> 5;
    const int lane = tid & 31;

    const int blk    = blockIdx.x;
    const int b      = blk / ETILES;
    const int et     = blk % ETILES;
    const int ebase  = et * ETILE;
    const int evalid = min(ETILE, E - ebase);

    if (tid < 256) ((float*)(smem + SMEM_BIAS))[tid] = bias[tid];

    const int warp_m = wid & 3;
    const int warp_n = wid >> 2;
    const int m0w = warp_m * 32;
    const int n0w = warp_n * 64;

    float acc[2][8][4];
    #pragma unroll
    for (int i = 0; i < 2; ++i)
        #pragma unroll
        for (int j = 0; j < 8; ++j)
            #pragma unroll
            for (int q = 0; q < 4; ++q) acc[i][j][q] = 0.f;

    const __half* xtb = g_xt16 + (size_t)b * E * CIN;
    const int*    nb  = ne_idx + ((size_t)b * E + ebase) * 4;

    // ldmatrix lane addressing
    const int a_row = lane & 15;
    const int a_kof = (lane >> 4) << 3;
    const int b_row = (lane & 7) + ((lane & 16) ? 8 : 0);
    const int b_kof = (lane & 8) ? 8 : 0;

    // gather fill mapping: 16 threads/edge, 8 fp16 channels/thread
    const int gj0 = (tid & 15) * 8;
    const int gm0 = tid >> 4;                  // edge within 32-edge pass
    const uint32_t g_koff = (uint32_t)(gj0 >> 6) * 16384;   // khalf sub-tile

    // ---------------- Prologue: B(tap0) + A slot0 (self rows, contiguous) ----
    {
        #pragma unroll
        for (int q = 0; q < 8; ++q) {          // B: 4096 x 16B
            int i = tid + q * 512;
            uint32_t off = (uint32_t)(i >> 11) * 32768 +
                SMEM_SWIZZLE_128B((uint32_t)(((i & 2047) >> 3) * 128 + (i & 7) * 16));
            cp_async16(smem_base + B_H(0) + off, (const char*)g_w + i * 16);
        }
        #pragma unroll
        for (int q = 0; q < 4; ++q) {          // A: 2048 x 16B
            int i = tid + q * 512;
            const int m = i >> 4;
            const int part = i & 15;
            uint32_t off = (uint32_t)(part >> 3) * 16384 +
                SMEM_SWIZZLE_128B((uint32_t)(m * 128 + (part & 7) * 16));
            const __half* src = xtb + (size_t)(ebase + m) * CIN + part * 8;
            if (m < evalid) cp_async16(smem_base + A_H(0) + off, src);
            else            cp_async16_zfill(smem_base + A_H(0) + off, xtb);
        }
        CP_COMMIT();
        CP_WAIT0();
        __syncthreads();
    }

    // ---------------- 5 merged stages (fully unrolled) ----------------
    #pragma unroll
    for (int s = 0; s < 5; ++s) {
        const int slot = s % 3;
        const int buf  = s & 1;
        const bool do_fill = (s == 0) || (s == 2);
        const int slotS = (s + 1) % 3;
        const int slotA = (s + 2) % 3;
        const bool useXZ = (s == 0);

        // B fill for next stage
        if (s < 4) {
            const __half* srcB = g_w + (size_t)STAGE_TAP(s + 1) * (2 * COUT * 64);
            const uint32_t dB = smem_base + B_H(buf ^ 1);
            #pragma unroll
            for (int q = 0; q < 8; ++q) {
                int i = tid + q * 512;
                uint32_t off = (uint32_t)(i >> 11) * 32768 +
                    SMEM_SWIZZLE_128B((uint32_t)(((i & 2047) >> 3) * 128 + (i & 7) * 16));
                cp_async16(dB + off, (const char*)srcB + i * 16);
            }
            CP_COMMIT();
        }

        const uint32_t aB = smem_base + A_H(slot);
        const uint32_t bB = smem_base + B_H(buf);

        // gather prefetch for pass 0
        uint4 ga = make_uint4(0, 0, 0, 0);
        uint4 gc = make_uint4(0, 0, 0, 0);
        if (do_fill && gm0 < evalid) {
            const int4 nbr = *(const int4*)(nb + gm0 * 4);
            const int ia = useXZ ? nbr.x : nbr.y;
            const int ib = useXZ ? nbr.z : nbr.w;
            ga = *(const uint4*)(xtb + (size_t)ia * CIN + gj0);
            gc = *(const uint4*)(xtb + (size_t)ib * CIN + gj0);
        }

        #pragma unroll
        for (int kk = 0; kk < 8; ++kk) {
            // prefetch gathers for pass kk+1
            uint4 gan = make_uint4(0, 0, 0, 0);
            uint4 gcn = make_uint4(0, 0, 0, 0);
            if (do_fill && kk < 3) {
                const int gm = (kk + 1) * 32 + gm0;
                if (gm < evalid) {
                    const int4 nbr = *(const int4*)(nb + gm * 4);
                    const int ia = useXZ ? nbr.x : nbr.y;
                    const int ib = useXZ ? nbr.z : nbr.w;
                    gan = *(const uint4*)(xtb + (size_t)ia * CIN + gj0);
                    gcn = *(const uint4*)(xtb + (size_t)ib * CIN + gj0);
                }
            }

            // ---- compute chunk kk: 16 HMMA ----
            {
                const uint32_t akh = (uint32_t)(kk >> 2) * 16384;
                const uint32_t bkh = (uint32_t)(kk >> 2) * 32768;
                const int kc = (kk & 3) * 16;
                uint32_t ah[2][4], bf[8][2];
                #pragma unroll
                for (int mt = 0; mt < 2; ++mt) {
                    const int row = m0w + mt * 16 + a_row;
                    uint32_t off = SMEM_SWIZZLE_128B((uint32_t)(row * 128 + (kc + a_kof) * 2));
                    ldsm_x4(ah[mt][0], ah[mt][1], ah[mt][2], ah[mt][3], aB + akh + off);
                }
                #pragma unroll
                for (int nbq = 0; nbq < 4; ++nbq) {
                    const int row = n0w + nbq * 16 + b_row;
                    uint32_t off = SMEM_SWIZZLE_128B((uint32_t)(row * 128 + (kc + b_kof) * 2));
                    ldsm_x4(bf[nbq * 2][0], bf[nbq * 2][1],
                            bf[nbq * 2 + 1][0], bf[nbq * 2 + 1][1], bB + bkh + off);
                }
                #pragma unroll
                for (int mt = 0; mt < 2; ++mt)
                    #pragma unroll
                    for (int j = 0; j < 8; ++j) mma16816(acc[mt][j], ah[mt], bf[j]);
            }

            // ---- combine + STS for pass kk (sum -> slotS, abs -> slotA) ----
            if (do_fill && kk < 4) {
                const int gm = kk * 32 + gm0;
                const uint32_t off = g_koff +
                    SMEM_SWIZZLE_128B((uint32_t)(gm * 128 + (gj0 & 63) * 2));
                *(uint4*)(smem + A_H(slotS) + off) = h2_add4(ga, gc);
                *(uint4*)(smem + A_H(slotA) + off) = h2_absdiff4(ga, gc);
                ga = gan; gc = gcn;
            }
        }

        if (s < 4) CP_WAIT0();
        __syncthreads();
    }

    // ---------------- Epilogue: +bias, store out[b][o][e] ----------------
    {
        const float* bsm = (const float*)(smem + SMEM_BIAS);
        float* obase = out + (size_t)b * COUT * E;
        #pragma unroll
        for (int mt = 0; mt < 2; ++mt) {
            const int r0 = m0w + mt * 16 + (lane >> 2);
            const int r1 = r0 + 8;
            const bool ok0 = r0 < evalid;
            const bool ok1 = r1 < evalid;
            #pragma unroll
            for (int j = 0; j < 8; ++j) {
                const int o = n0w + j * 8 + 2 * (lane & 3);
                const float b0 = bsm[o], b1 = bsm[o + 1];
                float* p0 = obase + (size_t)o * E;
                float* p1 = obase + (size_t)(o + 1) * E;
                if (ok0) {
                    p0[ebase + r0] = acc[mt][j][0] + b0;
                    p1[ebase + r0] = acc[mt][j][1] + b1;
                }
                if (ok1) {
                    p0[ebase + r1] = acc[mt][j][2] + b0;
                    p1[ebase + r1] = acc[mt][j][3] + b1;
                }
            }
        }
    }
}

// ============================================================================
// Launch
// ============================================================================
extern "C" void kernel_launch(void* const* d_in, const int* in_sizes, int n_in,
                              void* d_out, int out_size) {
    const float* x    = (const float*)d_in[0];
    const int*   ne   = (const int*)d_in[1];
    const float* w    = (const float*)d_in[2];
    const float* bias = (const float*)d_in[3];
    float*       out  = (float*)d_out;

    cudaFuncSetAttribute(mesh_main, cudaFuncAttributeMaxDynamicSharedMemorySize, SMEM_TOTAL);

    dim3 tgrid((E + 127) / 128, CIN / 32, BATCH);
    transpose_kernel<<<tgrid, 256>>>(x);
    wprep_kernel<<<(COUT * CIN * TAPS + 255) / 256, 256>>>(w);
    mesh_main<<<NBLOCKS, 512, SMEM_TOTAL>>>(ne, bias, out);
}